// round 6
// baseline (speedup 1.0000x reference)
#include <cuda_runtime.h>
#include <cuda_bf16.h>
#include <math.h>

#define T_ 16
#define B_ 32
#define S_ 256
#define H_ 256
#define E_ 300
#define V_ 1000

// ---------------- scratch arena (floats) ----------------
#define OFF_XPROJ   153600      // 1024*512 (transposed [4H, T*B])
#define OFF_H       710656      // 32*256
#define OFF_ENCT    727040      // 8192*256
#define OFF_COMB    3086336     // 512*512
#define OFF_LOGITS  3348480     // 512*1000
#define SCRATCH_N   3860480

__device__ float g_scratch[SCRATCH_N];
__device__ unsigned int g_bar;

#define F_TRANSC 1
#define F_ACCC   2

// ---------------- double-buffered GEMM: C = A[M,K] * B[N,K]^T + bias ----------
// BM=BN=64, BK=16, 256 threads, 4x4 thread tile, one sync per k-tile.
// gidx: optional A-row gather. flags: F_TRANSC -> C[n*ldc+m]; F_ACCC -> C += .
__global__ void sgemm_db_k(const float* __restrict__ A, int lda,
                           const float* __restrict__ Bm, int ldb,
                           const float* __restrict__ bias,
                           const int* __restrict__ gidx,
                           float* __restrict__ C, int ldc,
                           int M, int N, int K, int flags) {
    __shared__ float As[2][16][64];
    __shared__ float Bs[2][16][64];
    __shared__ int rows_sh[64];

    int tid = threadIdx.x;
    int m0 = blockIdx.y * 64, n0 = blockIdx.x * 64;
    int lkk = tid & 15;
    int lr0 = tid >> 4;
    int tx = tid & 15, ty = tid >> 4;
    int row0 = ty * 4, col0 = tx * 4;

    if (tid < 64) {
        int gm = m0 + tid;
        int r = (gm < M) ? gm : 0;
        rows_sh[tid] = gidx ? gidx[r] : r;
    }
    __syncthreads();

    int nk = (K + 15) / 16;
    float ra[4], rb[4];

    #pragma unroll
    for (int p = 0; p < 4; p++) {
        int r = lr0 + p * 16;
        int gk = lkk;
        int gm = m0 + r;
        As[0][lkk][r] = (gm < M && gk < K) ? A[(long)rows_sh[r] * lda + gk] : 0.f;
        int gn = n0 + r;
        Bs[0][lkk][r] = (gn < N && gk < K) ? Bm[(long)gn * ldb + gk] : 0.f;
    }
    __syncthreads();

    float acc[4][4] = {};
    for (int kt = 0; kt < nk; kt++) {
        int cur = kt & 1, nxt = cur ^ 1;
        bool more = (kt + 1 < nk);
        if (more) {
            int gk = (kt + 1) * 16 + lkk;
            #pragma unroll
            for (int p = 0; p < 4; p++) {
                int r = lr0 + p * 16;
                int gm = m0 + r;
                ra[p] = (gm < M && gk < K) ? A[(long)rows_sh[r] * lda + gk] : 0.f;
                int gn = n0 + r;
                rb[p] = (gn < N && gk < K) ? Bm[(long)gn * ldb + gk] : 0.f;
            }
        }
        #pragma unroll
        for (int kk = 0; kk < 16; kk++) {
            float4 a4 = *reinterpret_cast<const float4*>(&As[cur][kk][row0]);
            float4 b4 = *reinterpret_cast<const float4*>(&Bs[cur][kk][col0]);
            float a[4] = {a4.x, a4.y, a4.z, a4.w};
            float b[4] = {b4.x, b4.y, b4.z, b4.w};
            #pragma unroll
            for (int i = 0; i < 4; i++)
                #pragma unroll
                for (int j = 0; j < 4; j++)
                    acc[i][j] = fmaf(a[i], b[j], acc[i][j]);
        }
        if (more) {
            #pragma unroll
            for (int p = 0; p < 4; p++) {
                int r = lr0 + p * 16;
                As[nxt][lkk][r] = ra[p];
                Bs[nxt][lkk][r] = rb[p];
            }
        }
        __syncthreads();
    }

    #pragma unroll
    for (int i = 0; i < 4; i++) {
        int gm = m0 + row0 + i;
        if (gm >= M) continue;
        #pragma unroll
        for (int j = 0; j < 4; j++) {
            int gn = n0 + col0 + j;
            if (gn >= N) continue;
            float v = acc[i][j];
            if (bias) v += bias[gn];
            long cidx = (flags & F_TRANSC) ? (long)gn * ldc + gm : (long)gm * ldc + gn;
            if (flags & F_ACCC) v += C[cidx];
            C[cidx] = v;
        }
    }
}

// ---------------- persistent fused LSTM ----------------
// 64 blocks x 256 threads. Block owns hh0=4*bid; computes its 16 gate cols for
// all 32 batches per step; W slice in smem (loaded once); h staged in smem;
// pointwise local (c in registers); one grid sync per step.
// xproj is TRANSPOSED [4H, T*B] -> coalesced gate loads.
#define LSTM_GRID 64
#define HSTRIDE 260

__global__ void lstm_persist_k(const float* __restrict__ h0,
                               const float* __restrict__ c0,
                               const float* __restrict__ xprojT,  // [4H, 512]
                               const float* __restrict__ W_hh,    // [4H, H]
                               const float* __restrict__ b_hh,
                               float* __restrict__ h_glob,        // [B, H]
                               float* __restrict__ comb,          // [T,B,2H]
                               float* __restrict__ o_hT,
                               float* __restrict__ o_cT) {
    extern __shared__ float sm[];
    float* w_sh = sm;                       // 16*256
    float* h_sh = sm + 16 * 256;            // 32*HSTRIDE
    float* g_sh = h_sh + 32 * HSTRIDE;      // 16*32

    int tid = threadIdx.x, lane = tid & 31, wrp = tid >> 5;
    int hh0 = blockIdx.x * 4;

    // W_hh slice -> smem (once)
    for (int i = tid; i < 16 * 64; i += 256) {
        int lc = i >> 6;                    // local col 0..15 (= g*4 + j)
        int kc = i & 63;
        int g = lc >> 2, j = lc & 3;
        int col = g * 256 + hh0 + j;
        reinterpret_cast<float4*>(w_sh)[lc * 64 + kc] =
            reinterpret_cast<const float4*>(W_hh)[col * 64 + kc];
    }

    // pointwise threads: tid<128, pj = warp (hidden unit within block), pb = lane (batch)
    int pj = wrp, pb = lane;
    float c_reg = 0.f;
    const float* xr0 = nullptr; const float* xr1 = nullptr;
    const float* xr2 = nullptr; const float* xr3 = nullptr;
    float bh0 = 0.f, bh1 = 0.f, bh2 = 0.f, bh3 = 0.f;
    if (tid < 128) {
        int hh = hh0 + pj;
        c_reg = c0[pb * H_ + hh];
        xr0 = xprojT + (long)(hh) * 512;
        xr1 = xprojT + (long)(H_ + hh) * 512;
        xr2 = xprojT + (long)(2 * H_ + hh) * 512;
        xr3 = xprojT + (long)(3 * H_ + hh) * 512;
        bh0 = b_hh[hh]; bh1 = b_hh[H_ + hh];
        bh2 = b_hh[2 * H_ + hh]; bh3 = b_hh[3 * H_ + hh];
    }

    int lc0 = wrp * 2, lc1 = lc0 + 1;
    const float* w0 = w_sh + lc0 * 256;
    const float* w1 = w_sh + lc1 * 256;
    unsigned int bar_t = 0;

    for (int t = 0; t < T_; t++) {
        const float* hsrc = (t == 0) ? h0 : h_glob;
        __syncthreads();
        // stage h[32][256] -> smem
        for (int i = tid; i < 2048; i += 256) {
            int b = i >> 6, kc = i & 63;
            float4 v = __ldcg(reinterpret_cast<const float4*>(hsrc + b * H_ + kc * 4));
            *reinterpret_cast<float4*>(h_sh + b * HSTRIDE + kc * 4) = v;
        }
        // prefetch this step's xproj gates (coalesced; overlaps gemm)
        float xg0 = 0.f, xg1 = 0.f, xg2 = 0.f, xg3 = 0.f;
        if (tid < 128) {
            int o = t * 32 + pb;
            xg0 = xr0[o]; xg1 = xr1[o]; xg2 = xr2[o]; xg3 = xr3[o];
        }
        __syncthreads();

        // gemm: each warp computes 2 gate cols for 32 batches (lane = b)
        float acc0 = 0.f, acc1 = 0.f;
        const float* hr = h_sh + lane * HSTRIDE;
        #pragma unroll 8
        for (int k = 0; k < 256; k += 4) {
            float4 hv = *reinterpret_cast<const float4*>(hr + k);
            float4 a4 = *reinterpret_cast<const float4*>(w0 + k);
            float4 b4 = *reinterpret_cast<const float4*>(w1 + k);
            acc0 += hv.x * a4.x + hv.y * a4.y + hv.z * a4.z + hv.w * a4.w;
            acc1 += hv.x * b4.x + hv.y * b4.y + hv.z * b4.z + hv.w * b4.w;
        }
        g_sh[lc0 * 32 + lane] = acc0;
        g_sh[lc1 * 32 + lane] = acc1;
        __syncthreads();

        // pointwise update (exact tanh/sigmoid on the recurrence path)
        if (tid < 128) {
            int hh = hh0 + pj;
            float gi = g_sh[(0 + pj) * 32 + pb]  + xg0 + bh0;
            float gf = g_sh[(4 + pj) * 32 + pb]  + xg1 + bh1;
            float gg = g_sh[(8 + pj) * 32 + pb]  + xg2 + bh2;
            float go = g_sh[(12 + pj) * 32 + pb] + xg3 + bh3;
            float si = 1.f / (1.f + __expf(-gi));
            float sf = 1.f / (1.f + __expf(-gf));
            float so = 1.f / (1.f + __expf(-go));
            c_reg = sf * c_reg + si * tanhf(gg);
            float hn = so * tanhf(c_reg);
            h_glob[pb * H_ + hh] = hn;
            comb[(t * B_ + pb) * (2 * H_) + H_ + hh] = hn;
            if (t == T_ - 1) {
                o_hT[pb * H_ + hh] = hn;
                o_cT[pb * H_ + hh] = c_reg;
            }
        }

        __syncthreads();
        if (t < T_ - 1) {
            if (tid == 0) {
                __threadfence();
                bar_t += gridDim.x;
                atomicAdd(&g_bar, 1u);
                while (*reinterpret_cast<volatile unsigned int*>(&g_bar) < bar_t) {}
            }
            __syncthreads();
        }
    }
}

// ---------------- fused attention: dec matvec + scores + softmax + context ----
__device__ __forceinline__ float tanh_fast(float x) {
    float y;
    asm("tanh.approx.f32 %0, %1;" : "=f"(y) : "f"(x));
    return y;
}

__global__ void attn_fused_k(const float* __restrict__ enc_t,  // [S,B,H]
                             const float* __restrict__ Wd,     // [H,H]
                             const float* __restrict__ bd,
                             const float* __restrict__ wa,
                             const float* __restrict__ ba,
                             const int* __restrict__ lens,
                             const float* __restrict__ enc,    // [S,B,H]
                             float* __restrict__ comb,         // [T,B,2H]
                             float* __restrict__ ctx_out) {    // [B,T,H]
    int t = blockIdx.x / B_, b = blockIdx.x % B_;
    __shared__ float out_sh[H_], dec_sh[H_], wa_sh[H_], sc[S_], red[S_];
    int tid = threadIdx.x;
    int wrp = tid >> 5, lane = tid & 31;

    out_sh[tid] = comb[(t * B_ + b) * (2 * H_) + H_ + tid];
    wa_sh[tid] = wa[tid];
    __syncthreads();

    // dec[hh] = bd[hh] + sum_k out[k] * Wd[hh,k]; warp owns 32 hh rows
    {
        const float4* o4 = reinterpret_cast<const float4*>(out_sh);
        float4 oa = o4[lane], ob = o4[lane + 32];
        #pragma unroll 4
        for (int i = 0; i < 32; i++) {
            int hh = wrp * 32 + i;
            const float4* wr = reinterpret_cast<const float4*>(Wd + (long)hh * H_);
            float4 w0 = wr[lane], w1 = wr[lane + 32];
            float s = oa.x * w0.x + oa.y * w0.y + oa.z * w0.z + oa.w * w0.w
                    + ob.x * w1.x + ob.y * w1.y + ob.z * w1.z + ob.w * w1.w;
            #pragma unroll
            for (int o = 16; o; o >>= 1) s += __shfl_xor_sync(0xffffffffu, s, o);
            if (lane == 0) dec_sh[hh] = s + bd[hh];
        }
    }
    __syncthreads();

    float bav = ba[0];
    for (int s = wrp; s < S_; s += 8) {
        const float* er = enc_t + (long)(s * B_ + b) * H_;
        float sum = 0.f;
        #pragma unroll
        for (int i = 0; i < 8; i++) {
            int hh = lane + 32 * i;
            sum += tanh_fast(er[hh] + dec_sh[hh]) * wa_sh[hh];
        }
        #pragma unroll
        for (int o = 16; o; o >>= 1) sum += __shfl_xor_sync(0xffffffffu, sum, o);
        if (lane == 0) sc[s] = sum + bav;
    }
    __syncthreads();

    int len = lens[b];
    float v = (tid < len) ? sc[tid] : -1e30f;
    red[tid] = v; __syncthreads();
    for (int o = 128; o; o >>= 1) { if (tid < o) red[tid] = fmaxf(red[tid], red[tid + o]); __syncthreads(); }
    float m = red[0]; __syncthreads();
    float e = __expf(v - m);
    red[tid] = e; __syncthreads();
    for (int o = 128; o; o >>= 1) { if (tid < o) red[tid] += red[tid + o]; __syncthreads(); }
    float p = e * __fdividef(1.f, red[0]);
    __syncthreads();
    sc[tid] = p;
    __syncthreads();

    float sum = 0.f;
    const float* ep = enc + b * H_ + tid;
    #pragma unroll 4
    for (int s = 0; s < S_; s++)
        sum = fmaf(sc[s], ep[(long)s * B_ * H_], sum);
    comb[(t * B_ + b) * (2 * H_) + tid] = sum;
    ctx_out[(b * T_ + t) * H_ + tid] = sum;
}

// ---------------- softmax over V=1000 ----------------
__global__ void softmax_v_k(const float* __restrict__ logits, float* __restrict__ out) {
    int tb = blockIdx.x;
    int tid = threadIdx.x;
    __shared__ float red[256];
    const float* row = logits + (long)tb * V_;
    float m = -1e30f;
    for (int v = tid; v < V_; v += 256) m = fmaxf(m, row[v]);
    red[tid] = m; __syncthreads();
    for (int o = 128; o; o >>= 1) { if (tid < o) red[tid] = fmaxf(red[tid], red[tid + o]); __syncthreads(); }
    m = red[0]; __syncthreads();
    float sum = 0.f;
    for (int v = tid; v < V_; v += 256) {
        float e = __expf(row[v] - m);
        out[(long)tb * V_ + v] = e;
        sum += e;
    }
    red[tid] = sum; __syncthreads();
    for (int o = 128; o; o >>= 1) { if (tid < o) red[tid] += red[tid + o]; __syncthreads(); }
    float inv = __fdividef(1.f, red[0]);
    for (int v = tid; v < V_; v += 256) out[(long)tb * V_ + v] *= inv;
}

// ---------------- host ----------------
static inline void launch_gemm(cudaStream_t st,
                               const float* A, int lda, const float* B, int ldb,
                               const float* bias, const int* gidx,
                               float* C, int ldc, int M, int N, int K, int flags) {
    dim3 g((N + 63) / 64, (M + 63) / 64);
    sgemm_db_k<<<g, 256, 0, st>>>(A, lda, B, ldb, bias, gidx, C, ldc, M, N, K, flags);
}

static cudaStream_t g_s2;
static cudaEvent_t g_ev_fork, g_ev_enc, g_ev_lstm, g_ev_lb;
static bool g_init_done = false;

extern "C" void kernel_launch(void* const* d_in, const int* in_sizes, int n_in,
                              void* d_out, int out_size) {
    const int*   tv      = (const int*)  d_in[0];
    const float* h0      = (const float*)d_in[1];
    const float* c0      = (const float*)d_in[2];
    const float* enc     = (const float*)d_in[3];
    const int*   lens    = (const int*)  d_in[4];
    const float* emb     = (const float*)d_in[5];
    const float* W_ih    = (const float*)d_in[6];
    const float* W_hh    = (const float*)d_in[7];
    const float* b_ih    = (const float*)d_in[8];
    const float* b_hh    = (const float*)d_in[9];
    const float* We      = (const float*)d_in[10];
    const float* be      = (const float*)d_in[11];
    const float* Wd      = (const float*)d_in[12];
    const float* bd      = (const float*)d_in[13];
    const float* wa      = (const float*)d_in[14];
    const float* ba      = (const float*)d_in[15];
    const float* W_out   = (const float*)d_in[16];
    const float* b_out   = (const float*)d_in[17];

    if (!g_init_done) {
        cudaStreamCreateWithFlags(&g_s2, cudaStreamNonBlocking);
        cudaEventCreateWithFlags(&g_ev_fork, cudaEventDisableTiming);
        cudaEventCreateWithFlags(&g_ev_enc, cudaEventDisableTiming);
        cudaEventCreateWithFlags(&g_ev_lstm, cudaEventDisableTiming);
        cudaEventCreateWithFlags(&g_ev_lb, cudaEventDisableTiming);
        int lstm_smem = (16 * 256 + 32 * HSTRIDE + 16 * 32) * (int)sizeof(float);
        cudaFuncSetAttribute(lstm_persist_k, cudaFuncAttributeMaxDynamicSharedMemorySize, lstm_smem);
        g_init_done = true;
    }

    float* scratch = nullptr;
    cudaGetSymbolAddress((void**)&scratch, g_scratch);
    unsigned int* bar = nullptr;
    cudaGetSymbolAddress((void**)&bar, g_bar);

    float* s_xprojT = scratch + OFF_XPROJ;   // [4H, 512]
    float* s_h      = scratch + OFF_H;
    float* s_enct   = scratch + OFF_ENCT;
    float* s_comb   = scratch + OFF_COMB;
    float* s_logits = scratch + OFF_LOGITS;

    float* o_prob = (float*)d_out;
    float* o_hT   = o_prob + (long)T_ * B_ * V_;
    float* o_cT   = o_hT + B_ * H_;
    float* o_ctx  = o_cT + B_ * H_;

    // fork side stream
    cudaEventRecord(g_ev_fork, 0);
    cudaStreamWaitEvent(g_s2, g_ev_fork, 0);

    // side: enc_t = enc @ We^T + be : [8192, 256]
    launch_gemm(g_s2, enc, H_, We, H_, be, nullptr, s_enct, H_, S_ * B_, H_, H_, 0);
    cudaEventRecord(g_ev_enc, g_s2);

    // main: x_proj^T = (emb[tv] @ W_ih^T + b_ih)^T : [1024, 512]
    launch_gemm(0, emb, E_, W_ih, E_, b_ih, tv, s_xprojT, T_ * B_,
                T_ * B_, 4 * H_, E_, F_TRANSC);

    // main: persistent LSTM
    cudaMemsetAsync(bar, 0, sizeof(unsigned int), 0);
    int lstm_smem = (16 * 256 + 32 * HSTRIDE + 16 * 32) * (int)sizeof(float);
    lstm_persist_k<<<LSTM_GRID, 256, lstm_smem>>>(h0, c0, s_xprojT, W_hh, b_hh,
                                                  s_h, s_comb, o_hT, o_cT);
    cudaEventRecord(g_ev_lstm, 0);

    // side: logits partial from outs half: s_logits = outs @ W_out[:,256:]^T + b_out
    cudaStreamWaitEvent(g_s2, g_ev_lstm, 0);
    launch_gemm(g_s2, s_comb + H_, 2 * H_, W_out + H_, 2 * H_, b_out, nullptr,
                s_logits, V_, T_ * B_, V_, H_, 0);
    cudaEventRecord(g_ev_lb, g_s2);

    // main: attention (needs enc_t) -> writes ctx into comb[:, :H] and o_ctx
    cudaStreamWaitEvent(0, g_ev_enc, 0);
    attn_fused_k<<<T_ * B_, 256>>>(s_enct, Wd, bd, wa, ba, lens, enc, s_comb, o_ctx);

    // main: logits += ctx @ W_out[:, :256]^T   (accumulate)
    cudaStreamWaitEvent(0, g_ev_lb, 0);
    launch_gemm(0, s_comb, 2 * H_, W_out, 2 * H_, nullptr, nullptr,
                s_logits, V_, T_ * B_, V_, H_, F_ACCC);

    // main: softmax over V -> output_prob
    softmax_v_k<<<T_ * B_, 256>>>(s_logits, o_prob);
}

// round 8
// speedup vs baseline: 1.1180x; 1.1180x over previous
#include <cuda_runtime.h>
#include <cuda_bf16.h>
#include <math.h>

#define T_ 16
#define B_ 32
#define S_ 256
#define H_ 256
#define E_ 300
#define V_ 1000

// ---------------- scratch arena (floats) ----------------
#define OFF_XPROJ   153600      // [T*B, 4H] = 512*1024
#define OFF_H       710656      // 32*256
#define OFF_ENCT    727040      // 8192*256
#define OFF_COMB    3086336     // 512*512
#define OFF_LOGITS  3348480     // 512*1000
#define SCRATCH_N   3860480

__device__ float g_scratch[SCRATCH_N];
__device__ unsigned int g_sync[66];   // [0..63] per-block flags, [64] go flag

// ================= GEMM body (shared by dual + standalone) ==================
// C[M,N] = A[M,K] * B[N,K]^T + bias. BM=BN=64, BK=16, 256 thr, 4x4 tile,
// double buffered, one sync per k-tile. gidx: optional A-row gather.
#define GEMM_BODY(A, lda, Bm, ldb, bias, gidx, C, ldc, M, N, K, m0, n0)        \
    do {                                                                        \
        int tid = threadIdx.x;                                                  \
        int lkk = tid & 15;                                                     \
        int lr0 = tid >> 4;                                                     \
        int tx = tid & 15, ty = tid >> 4;                                       \
        int row0 = ty * 4, col0 = tx * 4;                                       \
        if (tid < 64) {                                                         \
            int gm = (m0) + tid;                                                \
            int r = (gm < (M)) ? gm : 0;                                        \
            rows_sh[tid] = (gidx) ? (gidx)[r] : r;                              \
        }                                                                       \
        __syncthreads();                                                        \
        int nk = ((K) + 15) / 16;                                               \
        float ra[4], rb[4];                                                     \
        _Pragma("unroll")                                                       \
        for (int p = 0; p < 4; p++) {                                           \
            int r = lr0 + p * 16;                                               \
            int gk = lkk;                                                       \
            int gm = (m0) + r;                                                  \
            As[0][lkk][r] = (gm < (M) && gk < (K)) ? (A)[(long)rows_sh[r] * (lda) + gk] : 0.f; \
            int gn = (n0) + r;                                                  \
            Bs[0][lkk][r] = (gn < (N) && gk < (K)) ? (Bm)[(long)gn * (ldb) + gk] : 0.f; \
        }                                                                       \
        __syncthreads();                                                        \
        float acc[4][4] = {};                                                   \
        for (int kt = 0; kt < nk; kt++) {                                       \
            int cur = kt & 1, nxt = cur ^ 1;                                    \
            bool more = (kt + 1 < nk);                                          \
            if (more) {                                                         \
                int gk = (kt + 1) * 16 + lkk;                                   \
                _Pragma("unroll")                                               \
                for (int p = 0; p < 4; p++) {                                   \
                    int r = lr0 + p * 16;                                       \
                    int gm = (m0) + r;                                          \
                    ra[p] = (gm < (M) && gk < (K)) ? (A)[(long)rows_sh[r] * (lda) + gk] : 0.f; \
                    int gn = (n0) + r;                                          \
                    rb[p] = (gn < (N) && gk < (K)) ? (Bm)[(long)gn * (ldb) + gk] : 0.f; \
                }                                                               \
            }                                                                   \
            _Pragma("unroll")                                                   \
            for (int kk = 0; kk < 16; kk++) {                                   \
                float4 a4 = *reinterpret_cast<const float4*>(&As[cur][kk][row0]); \
                float4 b4 = *reinterpret_cast<const float4*>(&Bs[cur][kk][col0]); \
                float av[4] = {a4.x, a4.y, a4.z, a4.w};                         \
                float bv[4] = {b4.x, b4.y, b4.z, b4.w};                         \
                _Pragma("unroll")                                               \
                for (int i = 0; i < 4; i++)                                     \
                    _Pragma("unroll")                                           \
                    for (int j = 0; j < 4; j++)                                 \
                        acc[i][j] = fmaf(av[i], bv[j], acc[i][j]);              \
            }                                                                   \
            if (more) {                                                         \
                _Pragma("unroll")                                               \
                for (int p = 0; p < 4; p++) {                                   \
                    int r = lr0 + p * 16;                                       \
                    As[nxt][lkk][r] = ra[p];                                    \
                    Bs[nxt][lkk][r] = rb[p];                                    \
                }                                                               \
            }                                                                   \
            __syncthreads();                                                    \
        }                                                                       \
        _Pragma("unroll")                                                       \
        for (int i = 0; i < 4; i++) {                                           \
            int gm = (m0) + row0 + i;                                           \
            if (gm >= (M)) continue;                                            \
            _Pragma("unroll")                                                   \
            for (int j = 0; j < 4; j++) {                                       \
                int gn = (n0) + col0 + j;                                       \
                if (gn >= (N)) continue;                                        \
                float v = acc[i][j];                                            \
                if (bias) v += (bias)[gn];                                      \
                (C)[(long)gm * (ldc) + gn] = v;                                 \
            }                                                                   \
        }                                                                       \
    } while (0)

// ---- dual GEMM: xproj (bx<16, by<8) and enc_t (bx in 16..19, any by) -------
__global__ void dual_gemm_k(const float* __restrict__ emb, const int* __restrict__ tv,
                            const float* __restrict__ W_ih, const float* __restrict__ b_ih,
                            float* __restrict__ xproj,
                            const float* __restrict__ enc, const float* __restrict__ We,
                            const float* __restrict__ be, float* __restrict__ enct) {
    __shared__ float As[2][16][64];
    __shared__ float Bs[2][16][64];
    __shared__ int rows_sh[64];
    int bx = blockIdx.x, by = blockIdx.y;
    if (bx < 16) {
        if (by >= 8) return;
        GEMM_BODY(emb, E_, W_ih, E_, b_ih, tv, xproj, 4 * H_,
                  T_ * B_, 4 * H_, E_, by * 64, bx * 64);
    } else {
        GEMM_BODY(enc, H_, We, H_, be, (const int*)nullptr, enct, H_,
                  S_ * B_, H_, H_, by * 64, (bx - 16) * 64);
    }
}

// ---- standalone GEMM (logits) ----------------------------------------------
__global__ void sgemm_db_k(const float* __restrict__ A, int lda,
                           const float* __restrict__ Bm, int ldb,
                           const float* __restrict__ bias,
                           float* __restrict__ C, int ldc,
                           int M, int N, int K) {
    __shared__ float As[2][16][64];
    __shared__ float Bs[2][16][64];
    __shared__ int rows_sh[64];
    int m0 = blockIdx.y * 64, n0 = blockIdx.x * 64;
    GEMM_BODY(A, lda, Bm, ldb, bias, (const int*)nullptr, C, ldc, M, N, K, m0, n0);
}

// ================= persistent fused LSTM ====================================
// 64 blocks x 256 threads (all co-resident). Block owns hh0=4*bid -> 16 gate
// cols. W slice in smem (once); h staged to smem per step; warp computes 2
// gate cols for 32 batches; pointwise local (c in regs); flag-tree grid sync.
#define LSTM_GRID 64
#define HSTRIDE 260

__global__ void lstm_persist_k(const float* __restrict__ h0,
                               const float* __restrict__ c0,
                               const float* __restrict__ xproj,   // [T*B,4H] (has b_ih)
                               const float* __restrict__ W_hh,    // [4H, H]
                               const float* __restrict__ b_hh,
                               float* __restrict__ h_glob,        // [B, H]
                               float* __restrict__ comb,          // [T,B,2H]
                               float* __restrict__ o_hT,
                               float* __restrict__ o_cT) {
    extern __shared__ float sm[];
    float* w_sh = sm;                       // 16*256
    float* h_sh = sm + 16 * 256;            // 32*HSTRIDE
    float* g_sh = h_sh + 32 * HSTRIDE;      // 16*32

    int tid = threadIdx.x, lane = tid & 31, wrp = tid >> 5;
    int hh0 = blockIdx.x * 4;

    // W_hh slice -> smem (once)
    for (int i = tid; i < 16 * 64; i += 256) {
        int lc = i >> 6, kc = i & 63;
        int g = lc >> 2, j = lc & 3;
        int col = g * 256 + hh0 + j;
        reinterpret_cast<float4*>(w_sh)[lc * 64 + kc] =
            reinterpret_cast<const float4*>(W_hh)[col * 64 + kc];
    }

    // pointwise threads: tid<128; pj = tid&3 (unit), pb = tid>>2 (batch)
    // -> h/comb writes land as 16B segments (8 sectors/warp, not 32)
    int pj = tid & 3, pb = tid >> 2;
    float c_reg = 0.f, bh0 = 0.f, bh1 = 0.f, bh2 = 0.f, bh3 = 0.f;
    if (tid < 128) {
        int hh = hh0 + pj;
        c_reg = c0[pb * H_ + hh];
        bh0 = b_hh[hh]; bh1 = b_hh[H_ + hh];
        bh2 = b_hh[2 * H_ + hh]; bh3 = b_hh[3 * H_ + hh];
    }

    int lc0 = wrp * 2, lc1 = lc0 + 1;
    const float* w0 = w_sh + lc0 * 256;
    const float* w1 = w_sh + lc1 * 256;
    volatile unsigned int* flags = g_sync;
    volatile unsigned int* go = g_sync + 64;

    for (int t = 0; t < T_; t++) {
        const float* hsrc = (t == 0) ? h0 : h_glob;
        __syncthreads();
        // stage h[32][256] -> smem
        for (int i = tid; i < 2048; i += 256) {
            int b = i >> 6, kc = i & 63;
            float4 v = __ldcg(reinterpret_cast<const float4*>(hsrc + b * H_ + kc * 4));
            *reinterpret_cast<float4*>(h_sh + b * HSTRIDE + kc * 4) = v;
        }
        // prefetch this step's xproj gate inputs (overlaps gemm)
        float xg0 = 0.f, xg1 = 0.f, xg2 = 0.f, xg3 = 0.f;
        if (tid < 128) {
            const float* xp = xproj + (long)(t * B_ + pb) * (4 * H_);
            int hh = hh0 + pj;
            xg0 = xp[hh]; xg1 = xp[H_ + hh]; xg2 = xp[2 * H_ + hh]; xg3 = xp[3 * H_ + hh];
        }
        __syncthreads();

        // gemm: each warp computes 2 gate cols for 32 batches (lane = b)
        float acc0 = 0.f, acc1 = 0.f;
        const float* hr = h_sh + lane * HSTRIDE;
        #pragma unroll 8
        for (int k = 0; k < 256; k += 4) {
            float4 hv = *reinterpret_cast<const float4*>(hr + k);
            float4 a4 = *reinterpret_cast<const float4*>(w0 + k);
            float4 b4 = *reinterpret_cast<const float4*>(w1 + k);
            acc0 += hv.x * a4.x + hv.y * a4.y + hv.z * a4.z + hv.w * a4.w;
            acc1 += hv.x * b4.x + hv.y * b4.y + hv.z * b4.z + hv.w * b4.w;
        }
        g_sh[lc0 * 32 + lane] = acc0;
        g_sh[lc1 * 32 + lane] = acc1;
        __syncthreads();

        // pointwise update (exact tanh/sigmoid on the recurrence path)
        if (tid < 128) {
            int hh = hh0 + pj;
            float gi = g_sh[(0 + pj) * 32 + pb]  + xg0 + bh0;
            float gf = g_sh[(4 + pj) * 32 + pb]  + xg1 + bh1;
            float gg = g_sh[(8 + pj) * 32 + pb]  + xg2 + bh2;
            float go_ = g_sh[(12 + pj) * 32 + pb] + xg3 + bh3;
            float si = 1.f / (1.f + __expf(-gi));
            float sf = 1.f / (1.f + __expf(-gf));
            float so = 1.f / (1.f + __expf(-go_));
            c_reg = sf * c_reg + si * tanhf(gg);
            float hn = so * tanhf(c_reg);
            h_glob[pb * H_ + hh] = hn;
            comb[(long)(t * B_ + pb) * (2 * H_) + H_ + hh] = hn;
            if (t == T_ - 1) {
                o_hT[pb * H_ + hh] = hn;
                o_cT[pb * H_ + hh] = c_reg;
            }
        }

        // grid sync: parallel flag arrivals, block-0 master, broadcast go
        __syncthreads();
        if (t < T_ - 1) {
            unsigned int tgt = (unsigned int)(t + 1);
            if (tid == 0) { __threadfence(); flags[blockIdx.x] = tgt; }
            if (blockIdx.x == 0) {
                if (tid < 64) while (flags[tid] < tgt) {}
                __syncthreads();
                if (tid == 0) { __threadfence(); *go = tgt; }
            } else {
                if (tid == 0) while (*go < tgt) {}
                __syncthreads();
            }
        }
    }
}

// ========== fused attention: dec matvec + scores + softmax + context ========
__device__ __forceinline__ float tanh_fast(float x) {
    float y;
    asm("tanh.approx.f32 %0, %1;" : "=f"(y) : "f"(x));
    return y;
}

__global__ void attn_fused_k(const float* __restrict__ enc_t,  // [S,B,H]
                             const float* __restrict__ Wd,     // [H,H]
                             const float* __restrict__ bd,
                             const float* __restrict__ wa,
                             const float* __restrict__ ba,
                             const int* __restrict__ lens,
                             const float* __restrict__ enc,    // [S,B,H]
                             float* __restrict__ comb,         // [T,B,2H]
                             float* __restrict__ ctx_out) {    // [B,T,H]
    int t = blockIdx.x / B_, b = blockIdx.x % B_;
    __shared__ float out_sh[H_], dec_sh[H_], wa_sh[H_], sc[S_], red[S_];
    int tid = threadIdx.x;
    int wrp = tid >> 5, lane = tid & 31;

    out_sh[tid] = comb[(long)(t * B_ + b) * (2 * H_) + H_ + tid];
    wa_sh[tid] = wa[tid];
    __syncthreads();

    // dec[hh] = bd[hh] + dot(out, Wd[hh,:]); warp owns 32 hh rows
    {
        const float4* o4 = reinterpret_cast<const float4*>(out_sh);
        float4 oa = o4[lane], ob = o4[lane + 32];
        #pragma unroll 4
        for (int i = 0; i < 32; i++) {
            int hh = wrp * 32 + i;
            const float4* wr = reinterpret_cast<const float4*>(Wd + (long)hh * H_);
            float4 w0 = wr[lane], w1 = wr[lane + 32];
            float s = oa.x * w0.x + oa.y * w0.y + oa.z * w0.z + oa.w * w0.w
                    + ob.x * w1.x + ob.y * w1.y + ob.z * w1.z + ob.w * w1.w;
            #pragma unroll
            for (int o = 16; o; o >>= 1) s += __shfl_xor_sync(0xffffffffu, s, o);
            if (lane == 0) dec_sh[hh] = s + bd[hh];
        }
    }
    __syncthreads();

    float bav = ba[0];
    for (int s = wrp; s < S_; s += 8) {
        const float* er = enc_t + (long)(s * B_ + b) * H_;
        float sum = 0.f;
        #pragma unroll
        for (int i = 0; i < 8; i++) {
            int hh = lane + 32 * i;
            sum += tanh_fast(er[hh] + dec_sh[hh]) * wa_sh[hh];
        }
        #pragma unroll
        for (int o = 16; o; o >>= 1) sum += __shfl_xor_sync(0xffffffffu, sum, o);
        if (lane == 0) sc[s] = sum + bav;
    }
    __syncthreads();

    int len = lens[b];
    float v = (tid < len) ? sc[tid] : -1e30f;
    red[tid] = v; __syncthreads();
    for (int o = 128; o; o >>= 1) { if (tid < o) red[tid] = fmaxf(red[tid], red[tid + o]); __syncthreads(); }
    float m = red[0]; __syncthreads();
    float e = __expf(v - m);
    red[tid] = e; __syncthreads();
    for (int o = 128; o; o >>= 1) { if (tid < o) red[tid] += red[tid + o]; __syncthreads(); }
    float p = e * __fdividef(1.f, red[0]);
    __syncthreads();
    sc[tid] = p;
    __syncthreads();

    float sum = 0.f;
    const float* ep = enc + b * H_ + tid;
    #pragma unroll 4
    for (int s = 0; s < S_; s++)
        sum = fmaf(sc[s], ep[(long)s * B_ * H_], sum);
    comb[(long)(t * B_ + b) * (2 * H_) + tid] = sum;
    ctx_out[(long)(b * T_ + t) * H_ + tid] = sum;
}

// ---------------- softmax over V=1000 ----------------
__global__ void softmax_v_k(const float* __restrict__ logits, float* __restrict__ out) {
    int tb = blockIdx.x;
    int tid = threadIdx.x;
    __shared__ float red[256];
    const float* row = logits + (long)tb * V_;
    float m = -1e30f;
    for (int v = tid; v < V_; v += 256) m = fmaxf(m, row[v]);
    red[tid] = m; __syncthreads();
    for (int o = 128; o; o >>= 1) { if (tid < o) red[tid] = fmaxf(red[tid], red[tid + o]); __syncthreads(); }
    m = red[0]; __syncthreads();
    float sum = 0.f;
    for (int v = tid; v < V_; v += 256) {
        float e = __expf(row[v] - m);
        out[(long)tb * V_ + v] = e;
        sum += e;
    }
    red[tid] = sum; __syncthreads();
    for (int o = 128; o; o >>= 1) { if (tid < o) red[tid] += red[tid + o]; __syncthreads(); }
    float inv = __fdividef(1.f, red[0]);
    for (int v = tid; v < V_; v += 256) out[(long)tb * V_ + v] *= inv;
}

// ---------------- host ----------------
extern "C" void kernel_launch(void* const* d_in, const int* in_sizes, int n_in,
                              void* d_out, int out_size) {
    const int*   tv      = (const int*)  d_in[0];
    const float* h0      = (const float*)d_in[1];
    const float* c0      = (const float*)d_in[2];
    const float* enc     = (const float*)d_in[3];
    const int*   lens    = (const int*)  d_in[4];
    const float* emb     = (const float*)d_in[5];
    const float* W_ih    = (const float*)d_in[6];
    const float* W_hh    = (const float*)d_in[7];
    const float* b_ih    = (const float*)d_in[8];
    const float* b_hh    = (const float*)d_in[9];
    const float* We      = (const float*)d_in[10];
    const float* be      = (const float*)d_in[11];
    const float* Wd      = (const float*)d_in[12];
    const float* bd      = (const float*)d_in[13];
    const float* wa      = (const float*)d_in[14];
    const float* ba      = (const float*)d_in[15];
    const float* W_out   = (const float*)d_in[16];
    const float* b_out   = (const float*)d_in[17];

    float* scratch = nullptr;
    cudaGetSymbolAddress((void**)&scratch, g_scratch);
    unsigned int* syncp = nullptr;
    cudaGetSymbolAddress((void**)&syncp, g_sync);

    float* s_xproj  = scratch + OFF_XPROJ;
    float* s_h      = scratch + OFF_H;
    float* s_enct   = scratch + OFF_ENCT;
    float* s_comb   = scratch + OFF_COMB;
    float* s_logits = scratch + OFF_LOGITS;

    float* o_prob = (float*)d_out;
    float* o_hT   = o_prob + (long)T_ * B_ * V_;
    float* o_cT   = o_hT + B_ * H_;
    float* o_ctx  = o_cT + B_ * H_;

    // 0) reset grid-sync flags
    cudaMemsetAsync(syncp, 0, 66 * sizeof(unsigned int));

    // 1) dual GEMM: xproj = emb[tv] @ W_ih^T + b_ih  AND  enc_t = enc @ We^T + be
    dual_gemm_k<<<dim3(20, 128), 256>>>(emb, tv, W_ih, b_ih, s_xproj,
                                        enc, We, be, s_enct);

    // 2) persistent LSTM (fused gemm + pointwise, flag-tree grid sync)
    int lstm_smem = (16 * 256 + 32 * HSTRIDE + 16 * 32) * (int)sizeof(float);
    cudaFuncSetAttribute(lstm_persist_k, cudaFuncAttributeMaxDynamicSharedMemorySize, lstm_smem);
    lstm_persist_k<<<LSTM_GRID, 256, lstm_smem>>>(h0, c0, s_xproj, W_hh, b_hh,
                                                  s_h, s_comb, o_hT, o_cT);

    // 3) fused attention: dec matvec + scores + masked softmax + context
    attn_fused_k<<<T_ * B_, 256>>>(s_enct, Wd, bd, wa, ba, lens, enc, s_comb, o_ctx);

    // 4) logits = combined @ W_out^T + b_out : [512, 1000]
    sgemm_db_k<<<dim3(16, 8), 256>>>(s_comb, 2 * H_, W_out, 2 * H_, b_out,
                                     s_logits, V_, T_ * B_, V_, 2 * H_);

    // 5) softmax over V -> output_prob
    softmax_v_k<<<T_ * B_, 256>>>(s_logits, o_prob);
}

// round 9
// speedup vs baseline: 1.7120x; 1.5314x over previous
#include <cuda_runtime.h>
#include <cuda_bf16.h>
#include <math.h>

#define T_ 16
#define B_ 32
#define S_ 256
#define H_ 256
#define E_ 300
#define V_ 1000

// ---------------- scratch arena (floats) ----------------
#define OFF_XPROJ   153600      // [T*B, 4H] = 512*1024
#define OFF_H       710656      // 32*256
#define OFF_ENCT    727040      // 8192*256
#define OFF_COMB    3086336     // 512*512
#define OFF_LOGITS  3348480     // 512*1000
#define SCRATCH_N   3860480

__device__ float g_scratch[SCRATCH_N];
__device__ unsigned int g_bar;

// ============ GEMM tile worker (R5 codegen, function form) ==================
// C[M,N] = A[M,K] * B[N,K]^T + bias. BM=BN=64, BK=16, 256 threads, 4x4 tile,
// double buffered, one sync per k-tile. gidx: optional A-row gather.
__device__ __forceinline__ void gemm_tile(
    const float* __restrict__ A, int lda,
    const float* __restrict__ Bm, int ldb,
    const float* __restrict__ bias,
    const int* __restrict__ gidx,
    float* __restrict__ C, int ldc,
    int M, int N, int K, int m0, int n0,
    float As[2][16][64], float Bs[2][16][64], int* rows_sh) {

    int tid = threadIdx.x;
    int lkk = tid & 15;
    int lr0 = tid >> 4;
    int tx = tid & 15, ty = tid >> 4;
    int row0 = ty * 4, col0 = tx * 4;

    if (tid < 64) {
        int gm = m0 + tid;
        int r = (gm < M) ? gm : 0;
        rows_sh[tid] = gidx ? gidx[r] : r;
    }
    __syncthreads();

    int nk = (K + 15) / 16;
    float ra[4], rb[4];

    #pragma unroll
    for (int p = 0; p < 4; p++) {
        int r = lr0 + p * 16;
        int gk = lkk;
        int gm = m0 + r;
        As[0][lkk][r] = (gm < M && gk < K) ? A[(long)rows_sh[r] * lda + gk] : 0.f;
        int gn = n0 + r;
        Bs[0][lkk][r] = (gn < N && gk < K) ? Bm[(long)gn * ldb + gk] : 0.f;
    }
    __syncthreads();

    float acc[4][4] = {};
    for (int kt = 0; kt < nk; kt++) {
        int cur = kt & 1, nxt = cur ^ 1;
        bool more = (kt + 1 < nk);
        if (more) {
            int gk = (kt + 1) * 16 + lkk;
            #pragma unroll
            for (int p = 0; p < 4; p++) {
                int r = lr0 + p * 16;
                int gm = m0 + r;
                ra[p] = (gm < M && gk < K) ? A[(long)rows_sh[r] * lda + gk] : 0.f;
                int gn = n0 + r;
                rb[p] = (gn < N && gk < K) ? Bm[(long)gn * ldb + gk] : 0.f;
            }
        }
        #pragma unroll
        for (int kk = 0; kk < 16; kk++) {
            float4 a4 = *reinterpret_cast<const float4*>(&As[cur][kk][row0]);
            float4 b4 = *reinterpret_cast<const float4*>(&Bs[cur][kk][col0]);
            float a[4] = {a4.x, a4.y, a4.z, a4.w};
            float b[4] = {b4.x, b4.y, b4.z, b4.w};
            #pragma unroll
            for (int i = 0; i < 4; i++)
                #pragma unroll
                for (int j = 0; j < 4; j++)
                    acc[i][j] = fmaf(a[i], b[j], acc[i][j]);
        }
        if (more) {
            #pragma unroll
            for (int p = 0; p < 4; p++) {
                int r = lr0 + p * 16;
                As[nxt][lkk][r] = ra[p];
                Bs[nxt][lkk][r] = rb[p];
            }
        }
        __syncthreads();
    }

    #pragma unroll
    for (int i = 0; i < 4; i++) {
        int gm = m0 + row0 + i;
        if (gm >= M) continue;
        #pragma unroll
        for (int j = 0; j < 4; j++) {
            int gn = n0 + col0 + j;
            if (gn >= N) continue;
            float v = acc[i][j];
            if (bias) v += bias[gn];
            C[(long)gm * ldc + gn] = v;
        }
    }
}

// ---- dual GEMM: one launch, 1-D grid routing, zero wasted blocks ----------
// blocks [0,128):   xproj = emb[tv] @ W_ih^T + b_ih   (M=512,N=1024 -> 8x16)
// blocks [128,640): enc_t = enc @ We^T + be           (M=8192,N=256 -> 128x4)
__global__ void dual_gemm_k(const float* __restrict__ emb, const int* __restrict__ tv,
                            const float* __restrict__ W_ih, const float* __restrict__ b_ih,
                            float* __restrict__ xproj,
                            const float* __restrict__ enc, const float* __restrict__ We,
                            const float* __restrict__ be, float* __restrict__ enct) {
    __shared__ float As[2][16][64];
    __shared__ float Bs[2][16][64];
    __shared__ int rows_sh[64];
    int bid = blockIdx.x;
    if (bid < 128) {
        int by = bid >> 4, bx = bid & 15;
        gemm_tile(emb, E_, W_ih, E_, b_ih, tv, xproj, 4 * H_,
                  T_ * B_, 4 * H_, E_, by * 64, bx * 64, As, Bs, rows_sh);
    } else {
        int r = bid - 128;
        int by = r >> 2, bx = r & 3;
        gemm_tile(enc, H_, We, H_, be, nullptr, enct, H_,
                  S_ * B_, H_, H_, by * 64, bx * 64, As, Bs, rows_sh);
    }
}

// ---- standalone GEMM (logits) ---------------------------------------------
__global__ void sgemm_k(const float* __restrict__ A, int lda,
                        const float* __restrict__ Bm, int ldb,
                        const float* __restrict__ bias,
                        float* __restrict__ C, int ldc,
                        int M, int N, int K) {
    __shared__ float As[2][16][64];
    __shared__ float Bs[2][16][64];
    __shared__ int rows_sh[64];
    gemm_tile(A, lda, Bm, ldb, bias, nullptr, C, ldc, M, N, K,
              blockIdx.y * 64, blockIdx.x * 64, As, Bs, rows_sh);
}

// ================= persistent fused LSTM (R4 core, measured 93us) ===========
#define LSTM_GRID 64
#define HSTRIDE 260

__global__ void lstm_persist_k(const float* __restrict__ h0,
                               const float* __restrict__ c0,
                               const float* __restrict__ xproj,   // [T*B,4H] (has b_ih)
                               const float* __restrict__ W_hh,    // [4H, H]
                               const float* __restrict__ b_hh,
                               float* __restrict__ h_glob,        // [B, H]
                               float* __restrict__ comb,          // [T,B,2H]
                               float* __restrict__ o_hT,
                               float* __restrict__ o_cT) {
    extern __shared__ float sm[];
    float* w_sh = sm;                       // 16*256
    float* h_sh = sm + 16 * 256;            // 32*HSTRIDE
    float* g_sh = h_sh + 32 * HSTRIDE;      // 16*32

    int tid = threadIdx.x, lane = tid & 31, wrp = tid >> 5;
    int hh0 = blockIdx.x * 4;

    // W_hh slice -> smem (once)
    for (int i = tid; i < 16 * 64; i += 256) {
        int lc = i >> 6, kc = i & 63;
        int g = lc >> 2, j = lc & 3;
        int col = g * 256 + hh0 + j;
        reinterpret_cast<float4*>(w_sh)[lc * 64 + kc] =
            reinterpret_cast<const float4*>(W_hh)[col * 64 + kc];
    }

    // pointwise threads (tid<128): pj = warp, pb = lane
    int pj = wrp, pb = lane;
    float c_reg = 0.f;
    if (tid < 128) c_reg = c0[pb * H_ + hh0 + pj];

    int lc0 = wrp * 2, lc1 = lc0 + 1;
    const float* w0 = w_sh + lc0 * 256;
    const float* w1 = w_sh + lc1 * 256;
    unsigned int bar_t = 0;

    for (int t = 0; t < T_; t++) {
        const float* hsrc = (t == 0) ? h0 : h_glob;
        __syncthreads();
        // stage h[32][256] -> smem
        for (int i = tid; i < 2048; i += 256) {
            int b = i >> 6, kc = i & 63;
            float4 v = __ldcg(reinterpret_cast<const float4*>(hsrc + b * H_ + kc * 4));
            *reinterpret_cast<float4*>(h_sh + b * HSTRIDE + kc * 4) = v;
        }
        __syncthreads();

        // gates: each warp computes 2 cols for 32 batches (lane = b)
        float acc0 = 0.f, acc1 = 0.f;
        const float* hr = h_sh + lane * HSTRIDE;
        #pragma unroll 8
        for (int k = 0; k < 256; k += 4) {
            float4 hv = *reinterpret_cast<const float4*>(hr + k);
            float4 a4 = *reinterpret_cast<const float4*>(w0 + k);
            float4 b4 = *reinterpret_cast<const float4*>(w1 + k);
            acc0 += hv.x * a4.x + hv.y * a4.y + hv.z * a4.z + hv.w * a4.w;
            acc1 += hv.x * b4.x + hv.y * b4.y + hv.z * b4.z + hv.w * b4.w;
        }
        g_sh[lc0 * 32 + lane] = acc0;
        g_sh[lc1 * 32 + lane] = acc1;
        __syncthreads();

        // pointwise update (exact tanh/sigmoid on the recurrence path)
        if (tid < 128) {
            int hh = hh0 + pj;
            const float* xp = xproj + (long)(t * B_ + pb) * (4 * H_);
            float gi = g_sh[(0 + pj) * 32 + pb]  + xp[hh]           + b_hh[hh];
            float gf = g_sh[(4 + pj) * 32 + pb]  + xp[H_ + hh]      + b_hh[H_ + hh];
            float gg = g_sh[(8 + pj) * 32 + pb]  + xp[2 * H_ + hh]  + b_hh[2 * H_ + hh];
            float go = g_sh[(12 + pj) * 32 + pb] + xp[3 * H_ + hh]  + b_hh[3 * H_ + hh];
            float si = 1.f / (1.f + __expf(-gi));
            float sf = 1.f / (1.f + __expf(-gf));
            float so = 1.f / (1.f + __expf(-go));
            c_reg = sf * c_reg + si * tanhf(gg);
            float hn = so * tanhf(c_reg);
            h_glob[pb * H_ + hh] = hn;
            comb[(long)(t * B_ + pb) * (2 * H_) + H_ + hh] = hn;
            if (t == T_ - 1) {
                o_hT[pb * H_ + hh] = hn;
                o_cT[pb * H_ + hh] = c_reg;
            }
        }

        __syncthreads();
        if (t < T_ - 1) {
            if (tid == 0) {
                __threadfence();
                bar_t += gridDim.x;
                atomicAdd(&g_bar, 1u);
                while (*reinterpret_cast<volatile unsigned int*>(&g_bar) < bar_t) {}
            }
            __syncthreads();
        }
    }
}

// ========== fused attention: dec matvec + scores + softmax + context ========
__device__ __forceinline__ float tanh_fast(float x) {
    float y;
    asm("tanh.approx.f32 %0, %1;" : "=f"(y) : "f"(x));
    return y;
}

__global__ void attn_fused_k(const float* __restrict__ enc_t,  // [S,B,H]
                             const float* __restrict__ Wd,     // [H,H]
                             const float* __restrict__ bd,
                             const float* __restrict__ wa,
                             const float* __restrict__ ba,
                             const int* __restrict__ lens,
                             const float* __restrict__ enc,    // [S,B,H]
                             float* __restrict__ comb,         // [T,B,2H]
                             float* __restrict__ ctx_out) {    // [B,T,H]
    int t = blockIdx.x / B_, b = blockIdx.x % B_;
    __shared__ float out_sh[H_], dec_sh[H_], wa_sh[H_], sc[S_], red[S_];
    int tid = threadIdx.x;
    int wrp = tid >> 5, lane = tid & 31;

    out_sh[tid] = comb[(long)(t * B_ + b) * (2 * H_) + H_ + tid];
    wa_sh[tid] = wa[tid];
    __syncthreads();

    // dec[hh] = bd[hh] + dot(out, Wd[hh,:]); warp owns 32 hh rows
    {
        const float4* o4 = reinterpret_cast<const float4*>(out_sh);
        float4 oa = o4[lane], ob = o4[lane + 32];
        #pragma unroll 4
        for (int i = 0; i < 32; i++) {
            int hh = wrp * 32 + i;
            const float4* wr = reinterpret_cast<const float4*>(Wd + (long)hh * H_);
            float4 w0 = wr[lane], w1 = wr[lane + 32];
            float s = oa.x * w0.x + oa.y * w0.y + oa.z * w0.z + oa.w * w0.w
                    + ob.x * w1.x + ob.y * w1.y + ob.z * w1.z + ob.w * w1.w;
            #pragma unroll
            for (int o = 16; o; o >>= 1) s += __shfl_xor_sync(0xffffffffu, s, o);
            if (lane == 0) dec_sh[hh] = s + bd[hh];
        }
    }
    __syncthreads();

    float bav = ba[0];
    for (int s = wrp; s < S_; s += 8) {
        const float* er = enc_t + (long)(s * B_ + b) * H_;
        float sum = 0.f;
        #pragma unroll
        for (int i = 0; i < 8; i++) {
            int hh = lane + 32 * i;
            sum += tanh_fast(er[hh] + dec_sh[hh]) * wa_sh[hh];
        }
        #pragma unroll
        for (int o = 16; o; o >>= 1) sum += __shfl_xor_sync(0xffffffffu, sum, o);
        if (lane == 0) sc[s] = sum + bav;
    }
    __syncthreads();

    int len = lens[b];
    float v = (tid < len) ? sc[tid] : -1e30f;
    red[tid] = v; __syncthreads();
    for (int o = 128; o; o >>= 1) { if (tid < o) red[tid] = fmaxf(red[tid], red[tid + o]); __syncthreads(); }
    float m = red[0]; __syncthreads();
    float e = __expf(v - m);
    red[tid] = e; __syncthreads();
    for (int o = 128; o; o >>= 1) { if (tid < o) red[tid] += red[tid + o]; __syncthreads(); }
    float p = e * __fdividef(1.f, red[0]);
    __syncthreads();
    sc[tid] = p;
    __syncthreads();

    float sum = 0.f;
    const float* ep = enc + b * H_ + tid;
    #pragma unroll 4
    for (int s = 0; s < S_; s++)
        sum = fmaf(sc[s], ep[(long)s * B_ * H_], sum);
    comb[(long)(t * B_ + b) * (2 * H_) + tid] = sum;
    ctx_out[(long)(b * T_ + t) * H_ + tid] = sum;
}

// ---------------- softmax over V=1000 ----------------
__global__ void softmax_v_k(const float* __restrict__ logits, float* __restrict__ out) {
    int tb = blockIdx.x;
    int tid = threadIdx.x;
    __shared__ float red[256];
    const float* row = logits + (long)tb * V_;
    float m = -1e30f;
    for (int v = tid; v < V_; v += 256) m = fmaxf(m, row[v]);
    red[tid] = m; __syncthreads();
    for (int o = 128; o; o >>= 1) { if (tid < o) red[tid] = fmaxf(red[tid], red[tid + o]); __syncthreads(); }
    m = red[0]; __syncthreads();
    float sum = 0.f;
    for (int v = tid; v < V_; v += 256) {
        float e = __expf(row[v] - m);
        out[(long)tb * V_ + v] = e;
        sum += e;
    }
    red[tid] = sum; __syncthreads();
    for (int o = 128; o; o >>= 1) { if (tid < o) red[tid] += red[tid + o]; __syncthreads(); }
    float inv = __fdividef(1.f, red[0]);
    for (int v = tid; v < V_; v += 256) out[(long)tb * V_ + v] *= inv;
}

// ---------------- host ----------------
extern "C" void kernel_launch(void* const* d_in, const int* in_sizes, int n_in,
                              void* d_out, int out_size) {
    const int*   tv      = (const int*)  d_in[0];
    const float* h0      = (const float*)d_in[1];
    const float* c0      = (const float*)d_in[2];
    const float* enc     = (const float*)d_in[3];
    const int*   lens    = (const int*)  d_in[4];
    const float* emb     = (const float*)d_in[5];
    const float* W_ih    = (const float*)d_in[6];
    const float* W_hh    = (const float*)d_in[7];
    const float* b_ih    = (const float*)d_in[8];
    const float* b_hh    = (const float*)d_in[9];
    const float* We      = (const float*)d_in[10];
    const float* be      = (const float*)d_in[11];
    const float* Wd      = (const float*)d_in[12];
    const float* bd      = (const float*)d_in[13];
    const float* wa      = (const float*)d_in[14];
    const float* ba      = (const float*)d_in[15];
    const float* W_out   = (const float*)d_in[16];
    const float* b_out   = (const float*)d_in[17];

    float* scratch = nullptr;
    cudaGetSymbolAddress((void**)&scratch, g_scratch);
    unsigned int* bar = nullptr;
    cudaGetSymbolAddress((void**)&bar, g_bar);

    float* s_xproj  = scratch + OFF_XPROJ;
    float* s_h      = scratch + OFF_H;
    float* s_enct   = scratch + OFF_ENCT;
    float* s_comb   = scratch + OFF_COMB;
    float* s_logits = scratch + OFF_LOGITS;

    float* o_prob = (float*)d_out;
    float* o_hT   = o_prob + (long)T_ * B_ * V_;
    float* o_cT   = o_hT + B_ * H_;
    float* o_ctx  = o_cT + B_ * H_;

    // 0) reset LSTM barrier
    cudaMemsetAsync(bar, 0, sizeof(unsigned int));

    // 1) dual GEMM: xproj = emb[tv] @ W_ih^T + b_ih  AND  enc_t = enc @ We^T + be
    dual_gemm_k<<<640, 256>>>(emb, tv, W_ih, b_ih, s_xproj, enc, We, be, s_enct);

    // 2) persistent LSTM (R4 core)
    int lstm_smem = (16 * 256 + 32 * HSTRIDE + 16 * 32) * (int)sizeof(float);
    cudaFuncSetAttribute(lstm_persist_k, cudaFuncAttributeMaxDynamicSharedMemorySize, lstm_smem);
    lstm_persist_k<<<LSTM_GRID, 256, lstm_smem>>>(h0, c0, s_xproj, W_hh, b_hh,
                                                  s_h, s_comb, o_hT, o_cT);

    // 3) fused attention: dec matvec + scores + masked softmax + context
    attn_fused_k<<<T_ * B_, 256>>>(s_enct, Wd, bd, wa, ba, lens, enc, s_comb, o_ctx);

    // 4) logits = combined @ W_out^T + b_out : [512, 1000]
    sgemm_k<<<dim3(16, 8), 256>>>(s_comb, 2 * H_, W_out, 2 * H_, b_out,
                                  s_logits, V_, T_ * B_, V_, 2 * H_);

    // 5) softmax over V -> output_prob
    softmax_v_k<<<T_ * B_, 256>>>(s_logits, o_prob);
}

// round 10
// speedup vs baseline: 1.9573x; 1.1433x over previous
#include <cuda_runtime.h>
#include <cuda_bf16.h>
#include <math.h>

#define T_ 16
#define B_ 32
#define S_ 256
#define H_ 256
#define E_ 300
#define V_ 1000

// ---------------- scratch arena (floats) ----------------
#define OFF_XPROJ   153600      // [T*B, 4H] = 512*1024
#define OFF_H       710656      // 32*256
#define OFF_ENCT    727040      // 8192*256
#define OFF_COMB    3086336     // 512*512
#define OFF_LOGITS  3348480     // 512*1000
#define SCRATCH_N   3860480

__device__ float g_scratch[SCRATCH_N];
__device__ unsigned int g_flags[128];

// ============================================================================
// Dual GEMM, bodies pasted with literal shapes (R5 codegen form).
// blocks [0,128):   xproj = emb[tv] @ W_ih^T + b_ih   (M=512,N=1024,K=300)
// blocks [128,640): enc_t = enc @ We^T + be           (M=8192,N=256,K=256)
// ============================================================================
__global__ void dual_gemm_k(const float* __restrict__ emb, const int* __restrict__ tv,
                            const float* __restrict__ W_ih, const float* __restrict__ b_ih,
                            float* __restrict__ xproj,
                            const float* __restrict__ enc, const float* __restrict__ We,
                            const float* __restrict__ be, float* __restrict__ enct) {
    __shared__ float As[2][16][64];
    __shared__ float Bs[2][16][64];
    __shared__ int rows_sh[64];

    int tid = threadIdx.x;
    int lkk = tid & 15;
    int lr0 = tid >> 4;
    int tx = tid & 15, ty = tid >> 4;
    int row0 = ty * 4, col0 = tx * 4;
    int bid = blockIdx.x;

    if (bid < 128) {
        // ---- xproj: M=512, N=1024, K=300, lda=ldb=300, ldc=1024, gather ----
        int m0 = (bid >> 4) * 64, n0 = (bid & 15) * 64;
        if (tid < 64) rows_sh[tid] = tv[m0 + tid];
        __syncthreads();
        float ra[4], rb[4];
        #pragma unroll
        for (int p = 0; p < 4; p++) {
            int r = lr0 + p * 16;
            As[0][lkk][r] = emb[(long)rows_sh[r] * E_ + lkk];
            Bs[0][lkk][r] = W_ih[(long)(n0 + r) * E_ + lkk];
        }
        __syncthreads();
        float acc[4][4] = {};
        for (int kt = 0; kt < 19; kt++) {
            int cur = kt & 1, nxt = cur ^ 1;
            bool more = (kt + 1 < 19);
            if (more) {
                int gk = (kt + 1) * 16 + lkk;
                #pragma unroll
                for (int p = 0; p < 4; p++) {
                    int r = lr0 + p * 16;
                    ra[p] = (gk < E_) ? emb[(long)rows_sh[r] * E_ + gk] : 0.f;
                    rb[p] = (gk < E_) ? W_ih[(long)(n0 + r) * E_ + gk] : 0.f;
                }
            }
            int klim = (kt == 18) ? 12 : 16;
            #pragma unroll 4
            for (int kk = 0; kk < klim; kk++) {
                float4 a4 = *reinterpret_cast<const float4*>(&As[cur][kk][row0]);
                float4 b4 = *reinterpret_cast<const float4*>(&Bs[cur][kk][col0]);
                float a[4] = {a4.x, a4.y, a4.z, a4.w};
                float b[4] = {b4.x, b4.y, b4.z, b4.w};
                #pragma unroll
                for (int i = 0; i < 4; i++)
                    #pragma unroll
                    for (int j = 0; j < 4; j++)
                        acc[i][j] = fmaf(a[i], b[j], acc[i][j]);
            }
            if (more) {
                #pragma unroll
                for (int p = 0; p < 4; p++) {
                    int r = lr0 + p * 16;
                    As[nxt][lkk][r] = ra[p];
                    Bs[nxt][lkk][r] = rb[p];
                }
            }
            __syncthreads();
        }
        #pragma unroll
        for (int i = 0; i < 4; i++) {
            int gm = m0 + row0 + i;
            #pragma unroll
            for (int j = 0; j < 4; j++) {
                int gn = n0 + col0 + j;
                xproj[(long)gm * (4 * H_) + gn] = acc[i][j] + b_ih[gn];
            }
        }
    } else {
        // ---- enc_t: M=8192, N=256, K=256, lda=ldb=ldc=256, no bounds ------
        int r2 = bid - 128;
        int m0 = (r2 >> 2) * 64, n0 = (r2 & 3) * 64;
        __syncthreads();   // match barrier count shape (rows_sh unused)
        float ra[4], rb[4];
        #pragma unroll
        for (int p = 0; p < 4; p++) {
            int r = lr0 + p * 16;
            As[0][lkk][r] = enc[(long)(m0 + r) * H_ + lkk];
            Bs[0][lkk][r] = We[(long)(n0 + r) * H_ + lkk];
        }
        __syncthreads();
        float acc[4][4] = {};
        for (int kt = 0; kt < 16; kt++) {
            int cur = kt & 1, nxt = cur ^ 1;
            bool more = (kt + 1 < 16);
            if (more) {
                int gk = (kt + 1) * 16 + lkk;
                #pragma unroll
                for (int p = 0; p < 4; p++) {
                    int r = lr0 + p * 16;
                    ra[p] = enc[(long)(m0 + r) * H_ + gk];
                    rb[p] = We[(long)(n0 + r) * H_ + gk];
                }
            }
            #pragma unroll
            for (int kk = 0; kk < 16; kk++) {
                float4 a4 = *reinterpret_cast<const float4*>(&As[cur][kk][row0]);
                float4 b4 = *reinterpret_cast<const float4*>(&Bs[cur][kk][col0]);
                float a[4] = {a4.x, a4.y, a4.z, a4.w};
                float b[4] = {b4.x, b4.y, b4.z, b4.w};
                #pragma unroll
                for (int i = 0; i < 4; i++)
                    #pragma unroll
                    for (int j = 0; j < 4; j++)
                        acc[i][j] = fmaf(a[i], b[j], acc[i][j]);
            }
            if (more) {
                #pragma unroll
                for (int p = 0; p < 4; p++) {
                    int r = lr0 + p * 16;
                    As[nxt][lkk][r] = ra[p];
                    Bs[nxt][lkk][r] = rb[p];
                }
            }
            __syncthreads();
        }
        #pragma unroll
        for (int i = 0; i < 4; i++) {
            int gm = m0 + row0 + i;
            #pragma unroll
            for (int j = 0; j < 4; j++) {
                int gn = n0 + col0 + j;
                enct[(long)gm * H_ + gn] = acc[i][j] + be[gn];
            }
        }
    }
}

// ============ logits GEMM: M=512, N=1000, K=512, body pasted ================
__global__ void logits_gemm_k(const float* __restrict__ A,      // comb, lda=512
                              const float* __restrict__ Bm,     // W_out [1000,512]
                              const float* __restrict__ bias,
                              float* __restrict__ C) {          // [512,1000]
    __shared__ float As[2][16][64];
    __shared__ float Bs[2][16][64];
    int tid = threadIdx.x;
    int lkk = tid & 15;
    int lr0 = tid >> 4;
    int tx = tid & 15, ty = tid >> 4;
    int row0 = ty * 4, col0 = tx * 4;
    int m0 = blockIdx.y * 64, n0 = blockIdx.x * 64;

    float ra[4], rb[4];
    #pragma unroll
    for (int p = 0; p < 4; p++) {
        int r = lr0 + p * 16;
        As[0][lkk][r] = A[(long)(m0 + r) * (2 * H_) + lkk];
        int gn = n0 + r;
        Bs[0][lkk][r] = (gn < V_) ? Bm[(long)gn * (2 * H_) + lkk] : 0.f;
    }
    __syncthreads();
    float acc[4][4] = {};
    for (int kt = 0; kt < 32; kt++) {
        int cur = kt & 1, nxt = cur ^ 1;
        bool more = (kt + 1 < 32);
        if (more) {
            int gk = (kt + 1) * 16 + lkk;
            #pragma unroll
            for (int p = 0; p < 4; p++) {
                int r = lr0 + p * 16;
                ra[p] = A[(long)(m0 + r) * (2 * H_) + gk];
                int gn = n0 + r;
                rb[p] = (gn < V_) ? Bm[(long)gn * (2 * H_) + gk] : 0.f;
            }
        }
        #pragma unroll
        for (int kk = 0; kk < 16; kk++) {
            float4 a4 = *reinterpret_cast<const float4*>(&As[cur][kk][row0]);
            float4 b4 = *reinterpret_cast<const float4*>(&Bs[cur][kk][col0]);
            float a[4] = {a4.x, a4.y, a4.z, a4.w};
            float b[4] = {b4.x, b4.y, b4.z, b4.w};
            #pragma unroll
            for (int i = 0; i < 4; i++)
                #pragma unroll
                for (int j = 0; j < 4; j++)
                    acc[i][j] = fmaf(a[i], b[j], acc[i][j]);
        }
        if (more) {
            #pragma unroll
            for (int p = 0; p < 4; p++) {
                int r = lr0 + p * 16;
                As[nxt][lkk][r] = ra[p];
                Bs[nxt][lkk][r] = rb[p];
            }
        }
        __syncthreads();
    }
    #pragma unroll
    for (int i = 0; i < 4; i++) {
        int gm = m0 + row0 + i;
        #pragma unroll
        for (int j = 0; j < 4; j++) {
            int gn = n0 + col0 + j;
            if (gn < V_) C[(long)gm * V_ + gn] = acc[i][j] + bias[gn];
        }
    }
}

// ============================================================================
// Persistent LSTM, batch-parallel groups.
// 128 blocks = 16 groups x 8. Group owns 2 batches; block owns 128 gate cols
// (32 hidden units). W slice (128KB) in smem, transposed [k4][col] for
// conflict-free LDS.128. Thread = (col, batch) owns the full K=256 dot product
// (no reduction). Sync = 8-flag group barrier only.
// ============================================================================
#define LSTM_GRID 128
#define WSTRIDE 129   // float4 stride per k4 row (pad to break STS conflicts)
#define LSTM_SMEM ((64 * WSTRIDE + 128) * 16 + 256 * 4)

__global__ void lstm_persist_k(const float* __restrict__ h0,
                               const float* __restrict__ c0,
                               const float* __restrict__ xproj,   // [T*B,4H] (has b_ih)
                               const float* __restrict__ W_hh,    // [4H, H]
                               const float* __restrict__ b_hh,
                               float* __restrict__ h_glob,        // [B, H]
                               float* __restrict__ comb,          // [T,B,2H]
                               float* __restrict__ o_hT,
                               float* __restrict__ o_cT) {
    extern __shared__ float4 sm4[];
    float4* w4s = sm4;                       // [64][WSTRIDE]
    float4* h4s = sm4 + 64 * WSTRIDE;        // [2][64]
    float*  g_s = (float*)(h4s + 128);       // [128 cols][2]

    int tid = threadIdx.x;
    int grp = blockIdx.x >> 3;               // 0..15 -> batches {2grp, 2grp+1}
    int blk = blockIdx.x & 7;                // 0..7  -> units [32blk, 32blk+32)

    // ---- load W slice (once), transposed ----
    const float4* W4 = reinterpret_cast<const float4*>(W_hh);
    for (int idx = tid; idx < 128 * 64; idx += 256) {
        int c = idx >> 6, k4 = idx & 63;
        int gcol = (c >> 5) * 256 + blk * 32 + (c & 31);
        w4s[k4 * WSTRIDE + c] = W4[(long)gcol * 64 + k4];
    }

    // ---- pointwise thread state (tid < 64): u = tid&31, b = tid>>5 ----
    int pu = tid & 31, pbl = tid >> 5;
    int hh = blk * 32 + pu;
    int bb = grp * 2 + pbl;
    float c_reg = 0.f, bh0 = 0.f, bh1 = 0.f, bh2 = 0.f, bh3 = 0.f;
    if (tid < 64) {
        c_reg = c0[bb * H_ + hh];
        bh0 = b_hh[hh];           bh1 = b_hh[H_ + hh];
        bh2 = b_hh[2 * H_ + hh];  bh3 = b_hh[3 * H_ + hh];
    }

    // ---- gemm thread state: col = tid&127, gb = tid>>7 ----
    int col = tid & 127, gb = tid >> 7;
    volatile unsigned int* flags = g_flags;

    for (int t = 0; t < T_; t++) {
        // wait for group peers' h from previous step
        if (t > 0) {
            if (tid < 8) {
                unsigned int tgt = (unsigned int)t;
                while (flags[grp * 8 + tid] < tgt) {}
            }
        }
        __syncthreads();

        // stage h[2 batches][256] -> smem
        const float* hsrc = (t == 0) ? h0 : h_glob;
        if (tid < 128) {
            int b = tid >> 6, k4 = tid & 63;
            h4s[b * 64 + k4] =
                __ldcg(reinterpret_cast<const float4*>(hsrc + (grp * 2 + b) * H_) + k4);
        }
        // prefetch xproj gate inputs for this step (overlaps gemm)
        float xg0 = 0.f, xg1 = 0.f, xg2 = 0.f, xg3 = 0.f;
        if (tid < 64) {
            const float* xp = xproj + (long)(t * B_ + bb) * (4 * H_);
            xg0 = xp[hh]; xg1 = xp[H_ + hh]; xg2 = xp[2 * H_ + hh]; xg3 = xp[3 * H_ + hh];
        }
        __syncthreads();

        // full dot product per thread: gate[col][gb] over K=256
        {
            float4 p = make_float4(0.f, 0.f, 0.f, 0.f);
            const float4* hb = h4s + gb * 64;
            #pragma unroll 16
            for (int k4 = 0; k4 < 64; k4++) {
                float4 w = w4s[k4 * WSTRIDE + col];
                float4 hv = hb[k4];
                p.x = fmaf(w.x, hv.x, p.x);
                p.y = fmaf(w.y, hv.y, p.y);
                p.z = fmaf(w.z, hv.z, p.z);
                p.w = fmaf(w.w, hv.w, p.w);
            }
            g_s[col * 2 + gb] = (p.x + p.y) + (p.z + p.w);
        }
        __syncthreads();

        // pointwise (exact tanh/sigmoid on the recurrence path)
        if (tid < 64) {
            float gi = g_s[(0 * 32 + pu) * 2 + pbl] + xg0 + bh0;
            float gf = g_s[(1 * 32 + pu) * 2 + pbl] + xg1 + bh1;
            float gg = g_s[(2 * 32 + pu) * 2 + pbl] + xg2 + bh2;
            float go = g_s[(3 * 32 + pu) * 2 + pbl] + xg3 + bh3;
            float si = 1.f / (1.f + __expf(-gi));
            float sf = 1.f / (1.f + __expf(-gf));
            float so = 1.f / (1.f + __expf(-go));
            c_reg = sf * c_reg + si * tanhf(gg);
            float hn = so * tanhf(c_reg);
            h_glob[bb * H_ + hh] = hn;
            comb[(long)(t * B_ + bb) * (2 * H_) + H_ + hh] = hn;
            if (t == T_ - 1) {
                o_hT[bb * H_ + hh] = hn;
                o_cT[bb * H_ + hh] = c_reg;
            }
        }

        // signal group peers
        if (t < T_ - 1) {
            __syncthreads();
            if (tid == 0) {
                __threadfence();
                g_flags[blockIdx.x] = (unsigned int)(t + 1);
            }
        }
    }
}

// ========== fused attention: dec matvec + scores + softmax + context ========
__device__ __forceinline__ float tanh_fast(float x) {
    float y;
    asm("tanh.approx.f32 %0, %1;" : "=f"(y) : "f"(x));
    return y;
}

__global__ void attn_fused_k(const float* __restrict__ enc_t,  // [S,B,H]
                             const float* __restrict__ Wd,     // [H,H]
                             const float* __restrict__ bd,
                             const float* __restrict__ wa,
                             const float* __restrict__ ba,
                             const int* __restrict__ lens,
                             const float* __restrict__ enc,    // [S,B,H]
                             float* __restrict__ comb,         // [T,B,2H]
                             float* __restrict__ ctx_out) {    // [B,T,H]
    int t = blockIdx.x / B_, b = blockIdx.x % B_;
    __shared__ float out_sh[H_], dec_sh[H_], wa_sh[H_], sc[S_], red[S_];
    int tid = threadIdx.x;
    int wrp = tid >> 5, lane = tid & 31;

    out_sh[tid] = comb[(long)(t * B_ + b) * (2 * H_) + H_ + tid];
    wa_sh[tid] = wa[tid];
    __syncthreads();

    // dec[hh] = bd[hh] + dot(out, Wd[hh,:]); warp owns 32 hh rows
    {
        const float4* o4 = reinterpret_cast<const float4*>(out_sh);
        float4 oa = o4[lane], ob = o4[lane + 32];
        #pragma unroll 4
        for (int i = 0; i < 32; i++) {
            int hh = wrp * 32 + i;
            const float4* wr = reinterpret_cast<const float4*>(Wd + (long)hh * H_);
            float4 w0 = wr[lane], w1 = wr[lane + 32];
            float s = oa.x * w0.x + oa.y * w0.y + oa.z * w0.z + oa.w * w0.w
                    + ob.x * w1.x + ob.y * w1.y + ob.z * w1.z + ob.w * w1.w;
            #pragma unroll
            for (int o = 16; o; o >>= 1) s += __shfl_xor_sync(0xffffffffu, s, o);
            if (lane == 0) dec_sh[hh] = s + bd[hh];
        }
    }
    __syncthreads();

    float bav = ba[0];
    for (int s = wrp; s < S_; s += 8) {
        const float* er = enc_t + (long)(s * B_ + b) * H_;
        float sum = 0.f;
        #pragma unroll
        for (int i = 0; i < 8; i++) {
            int hh = lane + 32 * i;
            sum += tanh_fast(er[hh] + dec_sh[hh]) * wa_sh[hh];
        }
        #pragma unroll
        for (int o = 16; o; o >>= 1) sum += __shfl_xor_sync(0xffffffffu, sum, o);
        if (lane == 0) sc[s] = sum + bav;
    }
    __syncthreads();

    int len = lens[b];
    float v = (tid < len) ? sc[tid] : -1e30f;
    red[tid] = v; __syncthreads();
    for (int o = 128; o; o >>= 1) { if (tid < o) red[tid] = fmaxf(red[tid], red[tid + o]); __syncthreads(); }
    float m = red[0]; __syncthreads();
    float e = __expf(v - m);
    red[tid] = e; __syncthreads();
    for (int o = 128; o; o >>= 1) { if (tid < o) red[tid] += red[tid + o]; __syncthreads(); }
    float p = e * __fdividef(1.f, red[0]);
    __syncthreads();
    sc[tid] = p;
    __syncthreads();

    float sum = 0.f;
    const float* ep = enc + b * H_ + tid;
    #pragma unroll 4
    for (int s = 0; s < S_; s++)
        sum = fmaf(sc[s], ep[(long)s * B_ * H_], sum);
    comb[(long)(t * B_ + b) * (2 * H_) + tid] = sum;
    ctx_out[(long)(b * T_ + t) * H_ + tid] = sum;
}

// ---------------- softmax over V=1000 ----------------
__global__ void softmax_v_k(const float* __restrict__ logits, float* __restrict__ out) {
    int tb = blockIdx.x;
    int tid = threadIdx.x;
    __shared__ float red[256];
    const float* row = logits + (long)tb * V_;
    float m = -1e30f;
    for (int v = tid; v < V_; v += 256) m = fmaxf(m, row[v]);
    red[tid] = m; __syncthreads();
    for (int o = 128; o; o >>= 1) { if (tid < o) red[tid] = fmaxf(red[tid], red[tid + o]); __syncthreads(); }
    m = red[0]; __syncthreads();
    float sum = 0.f;
    for (int v = tid; v < V_; v += 256) {
        float e = __expf(row[v] - m);
        out[(long)tb * V_ + v] = e;
        sum += e;
    }
    red[tid] = sum; __syncthreads();
    for (int o = 128; o; o >>= 1) { if (tid < o) red[tid] += red[tid + o]; __syncthreads(); }
    float inv = __fdividef(1.f, red[0]);
    for (int v = tid; v < V_; v += 256) out[(long)tb * V_ + v] *= inv;
}

// ---------------- host ----------------
extern "C" void kernel_launch(void* const* d_in, const int* in_sizes, int n_in,
                              void* d_out, int out_size) {
    const int*   tv      = (const int*)  d_in[0];
    const float* h0      = (const float*)d_in[1];
    const float* c0      = (const float*)d_in[2];
    const float* enc     = (const float*)d_in[3];
    const int*   lens    = (const int*)  d_in[4];
    const float* emb     = (const float*)d_in[5];
    const float* W_ih    = (const float*)d_in[6];
    const float* W_hh    = (const float*)d_in[7];
    const float* b_ih    = (const float*)d_in[8];
    const float* b_hh    = (const float*)d_in[9];
    const float* We      = (const float*)d_in[10];
    const float* be      = (const float*)d_in[11];
    const float* Wd      = (const float*)d_in[12];
    const float* bd      = (const float*)d_in[13];
    const float* wa      = (const float*)d_in[14];
    const float* ba      = (const float*)d_in[15];
    const float* W_out   = (const float*)d_in[16];
    const float* b_out   = (const float*)d_in[17];

    float* scratch = nullptr;
    cudaGetSymbolAddress((void**)&scratch, g_scratch);
    unsigned int* flagsp = nullptr;
    cudaGetSymbolAddress((void**)&flagsp, g_flags);

    float* s_xproj  = scratch + OFF_XPROJ;
    float* s_h      = scratch + OFF_H;
    float* s_enct   = scratch + OFF_ENCT;
    float* s_comb   = scratch + OFF_COMB;
    float* s_logits = scratch + OFF_LOGITS;

    float* o_prob = (float*)d_out;
    float* o_hT   = o_prob + (long)T_ * B_ * V_;
    float* o_cT   = o_hT + B_ * H_;
    float* o_ctx  = o_cT + B_ * H_;

    // 0) reset group-barrier flags
    cudaMemsetAsync(flagsp, 0, 128 * sizeof(unsigned int));

    // 1) dual GEMM: xproj AND enc_t in one launch
    dual_gemm_k<<<640, 256>>>(emb, tv, W_ih, b_ih, s_xproj, enc, We, be, s_enct);

    // 2) persistent LSTM (batch-parallel groups, W-resident in smem)
    cudaFuncSetAttribute(lstm_persist_k, cudaFuncAttributeMaxDynamicSharedMemorySize, LSTM_SMEM);
    lstm_persist_k<<<LSTM_GRID, 256, LSTM_SMEM>>>(h0, c0, s_xproj, W_hh, b_hh,
                                                  s_h, s_comb, o_hT, o_cT);

    // 3) fused attention: dec matvec + scores + masked softmax + context
    attn_fused_k<<<T_ * B_, 256>>>(s_enct, Wd, bd, wa, ba, lens, enc, s_comb, o_ctx);

    // 4) logits = combined @ W_out^T + b_out : [512, 1000]
    logits_gemm_k<<<dim3(16, 8), 256>>>(s_comb, W_out, b_out, s_logits);

    // 5) softmax over V -> output_prob
    softmax_v_k<<<T_ * B_, 256>>>(s_logits, o_prob);
}

// round 11
// speedup vs baseline: 2.7462x; 1.4030x over previous
#include <cuda_runtime.h>
#include <cuda_bf16.h>
#include <math.h>

#define T_ 16
#define B_ 32
#define S_ 256
#define H_ 256
#define E_ 300
#define V_ 1000

// ---------------- scratch arena (floats) ----------------
#define OFF_XPROJ   153600      // [T*B, 4H] = 512*1024
#define OFF_H       710656      // 32*256
#define OFF_ENCT    727040      // 8192*256
#define OFF_COMB    3086336     // 512*512
#define OFF_LOGITS  3348480     // 512*1000
#define SCRATCH_N   3860480

__device__ float g_scratch[SCRATCH_N];
__device__ unsigned int g_flags[128];

// ==================== tf32 mma helpers ====================
__device__ __forceinline__ unsigned f2tf(float x) {
    unsigned r; asm("cvt.rna.tf32.f32 %0, %1;" : "=r"(r) : "f"(x)); return r;
}
__device__ __forceinline__ void mma8(float* c, const unsigned* a, const unsigned* b) {
    asm("mma.sync.aligned.m16n8k8.row.col.f32.tf32.tf32.f32 "
        "{%0,%1,%2,%3}, {%4,%5,%6,%7}, {%8,%9}, {%0,%1,%2,%3};"
        : "+f"(c[0]), "+f"(c[1]), "+f"(c[2]), "+f"(c[3])
        : "r"(a[0]), "r"(a[1]), "r"(a[2]), "r"(a[3]), "r"(b[0]), "r"(b[1]));
}

// store 8 cvt'd floats into transposed smem tile [k][m]
#define STS8(DST, BUF, SK, SM, V0, V1)                  \
    DST[BUF][(SK) + 0][SM] = f2tf((V0).x);              \
    DST[BUF][(SK) + 1][SM] = f2tf((V0).y);              \
    DST[BUF][(SK) + 2][SM] = f2tf((V0).z);              \
    DST[BUF][(SK) + 3][SM] = f2tf((V0).w);              \
    DST[BUF][(SK) + 4][SM] = f2tf((V1).x);              \
    DST[BUF][(SK) + 5][SM] = f2tf((V1).y);              \
    DST[BUF][(SK) + 6][SM] = f2tf((V1).z);              \
    DST[BUF][(SK) + 7][SM] = f2tf((V1).w);

// one 64x64x16 tile of mma compute on buffer CUR (locals: AsT,BsT,cacc,g,j,m_off,n_off)
#define MMA_TILE(CUR)                                                        \
    _Pragma("unroll")                                                        \
    for (int s = 0; s < 2; s++) {                                            \
        unsigned af[2][4], bf[4][2];                                         \
        _Pragma("unroll")                                                    \
        for (int mi = 0; mi < 2; mi++) {                                     \
            af[mi][0] = AsT[CUR][s * 8 + j    ][m_off + mi * 16 + g];        \
            af[mi][1] = AsT[CUR][s * 8 + j    ][m_off + mi * 16 + g + 8];    \
            af[mi][2] = AsT[CUR][s * 8 + j + 4][m_off + mi * 16 + g];        \
            af[mi][3] = AsT[CUR][s * 8 + j + 4][m_off + mi * 16 + g + 8];    \
        }                                                                    \
        _Pragma("unroll")                                                    \
        for (int ni = 0; ni < 4; ni++) {                                     \
            bf[ni][0] = BsT[CUR][s * 8 + j    ][n_off + ni * 8 + g];         \
            bf[ni][1] = BsT[CUR][s * 8 + j + 4][n_off + ni * 8 + g];         \
        }                                                                    \
        _Pragma("unroll")                                                    \
        for (int mi = 0; mi < 2; mi++)                                       \
            _Pragma("unroll")                                                \
            for (int ni = 0; ni < 4; ni++)                                   \
                mma8(cacc[mi][ni], af[mi], bf[ni]);                          \
    }

// ============================================================================
// Dual tf32 GEMM. 128-thread blocks, 64x64x16 tiles.
// blocks [0,128):   xproj = emb[tv] @ W_ih^T + b_ih  (M=512,N=1024,K=300)
// blocks [128,640): enc_t = enc @ We^T + be          (M=8192,N=256,K=256)
// ============================================================================
__global__ void dual_gemm_k(const float* __restrict__ emb, const int* __restrict__ tv,
                            const float* __restrict__ W_ih, const float* __restrict__ b_ih,
                            float* __restrict__ xproj,
                            const float* __restrict__ enc, const float* __restrict__ We,
                            const float* __restrict__ be, float* __restrict__ enct) {
    __shared__ unsigned AsT[2][16][65];
    __shared__ unsigned BsT[2][16][65];
    __shared__ int rows_sh[64];

    int tid = threadIdx.x;
    int lane = tid & 31, warp = tid >> 5;
    int g = lane >> 2, j = lane & 3;
    int m_off = (warp & 1) * 32, n_off = (warp >> 1) * 32;
    int sm = tid >> 1, sk = (tid & 1) * 8;
    int bid = blockIdx.x;

    float cacc[2][4][4];
    #pragma unroll
    for (int mi = 0; mi < 2; mi++)
        #pragma unroll
        for (int ni = 0; ni < 4; ni++)
            #pragma unroll
            for (int q = 0; q < 4; q++) cacc[mi][ni][q] = 0.f;

    if (bid < 128) {
        // -------- xproj: M=512, N=1024, K=300 (19 k-tiles, last ragged) -----
        int m0 = (bid >> 4) * 64, n0 = (bid & 15) * 64;
        if (tid < 64) rows_sh[tid] = tv[m0 + tid];
        __syncthreads();
        // stage tile 0 (k 0..15 < 300: fast path)
        {
            const float4* ap = reinterpret_cast<const float4*>(emb + (long)rows_sh[sm] * E_ + sk);
            const float4* bp = reinterpret_cast<const float4*>(W_ih + (long)(n0 + sm) * E_ + sk);
            float4 a0 = ap[0], a1 = ap[1], b0 = bp[0], b1 = bp[1];
            STS8(AsT, 0, sk, sm, a0, a1);
            STS8(BsT, 0, sk, sm, b0, b1);
        }
        __syncthreads();
        for (int kt = 0; kt < 19; kt++) {
            int cur = kt & 1, nxt = cur ^ 1;
            bool more = (kt + 1 < 19);
            float4 va0, va1, vb0, vb1;
            if (more) {
                int gk = (kt + 1) * 16 + sk;
                if ((kt + 2) * 16 <= E_) {
                    const float4* ap = reinterpret_cast<const float4*>(emb + (long)rows_sh[sm] * E_ + gk);
                    const float4* bp = reinterpret_cast<const float4*>(W_ih + (long)(n0 + sm) * E_ + gk);
                    va0 = ap[0]; va1 = ap[1]; vb0 = bp[0]; vb1 = bp[1];
                } else {
                    const float* ar = emb + (long)rows_sh[sm] * E_;
                    const float* br = W_ih + (long)(n0 + sm) * E_;
                    float t[8], u[8];
                    #pragma unroll
                    for (int i = 0; i < 8; i++) {
                        int k = gk + i;
                        t[i] = (k < E_) ? ar[k] : 0.f;
                        u[i] = (k < E_) ? br[k] : 0.f;
                    }
                    va0 = make_float4(t[0], t[1], t[2], t[3]);
                    va1 = make_float4(t[4], t[5], t[6], t[7]);
                    vb0 = make_float4(u[0], u[1], u[2], u[3]);
                    vb1 = make_float4(u[4], u[5], u[6], u[7]);
                }
            }
            MMA_TILE(cur);
            if (more) {
                STS8(AsT, nxt, sk, sm, va0, va1);
                STS8(BsT, nxt, sk, sm, vb0, vb1);
            }
            __syncthreads();
        }
        #pragma unroll
        for (int mi = 0; mi < 2; mi++) {
            int rm = m0 + m_off + mi * 16;
            #pragma unroll
            for (int ni = 0; ni < 4; ni++) {
                int cn = n0 + n_off + ni * 8 + 2 * j;
                float2 p0 = make_float2(cacc[mi][ni][0] + b_ih[cn], cacc[mi][ni][1] + b_ih[cn + 1]);
                float2 p1 = make_float2(cacc[mi][ni][2] + b_ih[cn], cacc[mi][ni][3] + b_ih[cn + 1]);
                *reinterpret_cast<float2*>(xproj + (long)(rm + g) * (4 * H_) + cn) = p0;
                *reinterpret_cast<float2*>(xproj + (long)(rm + g + 8) * (4 * H_) + cn) = p1;
            }
        }
    } else {
        // -------- enc_t: M=8192, N=256, K=256 (16 clean k-tiles) ------------
        int r2 = bid - 128;
        int m0 = (r2 >> 2) * 64, n0 = (r2 & 3) * 64;
        {
            const float4* ap = reinterpret_cast<const float4*>(enc + (long)(m0 + sm) * H_ + sk);
            const float4* bp = reinterpret_cast<const float4*>(We + (long)(n0 + sm) * H_ + sk);
            float4 a0 = ap[0], a1 = ap[1], b0 = bp[0], b1 = bp[1];
            STS8(AsT, 0, sk, sm, a0, a1);
            STS8(BsT, 0, sk, sm, b0, b1);
        }
        __syncthreads();
        for (int kt = 0; kt < 16; kt++) {
            int cur = kt & 1, nxt = cur ^ 1;
            bool more = (kt + 1 < 16);
            float4 va0, va1, vb0, vb1;
            if (more) {
                int gk = (kt + 1) * 16 + sk;
                const float4* ap = reinterpret_cast<const float4*>(enc + (long)(m0 + sm) * H_ + gk);
                const float4* bp = reinterpret_cast<const float4*>(We + (long)(n0 + sm) * H_ + gk);
                va0 = ap[0]; va1 = ap[1]; vb0 = bp[0]; vb1 = bp[1];
            }
            MMA_TILE(cur);
            if (more) {
                STS8(AsT, nxt, sk, sm, va0, va1);
                STS8(BsT, nxt, sk, sm, vb0, vb1);
            }
            __syncthreads();
        }
        #pragma unroll
        for (int mi = 0; mi < 2; mi++) {
            int rm = m0 + m_off + mi * 16;
            #pragma unroll
            for (int ni = 0; ni < 4; ni++) {
                int cn = n0 + n_off + ni * 8 + 2 * j;
                float2 p0 = make_float2(cacc[mi][ni][0] + be[cn], cacc[mi][ni][1] + be[cn + 1]);
                float2 p1 = make_float2(cacc[mi][ni][2] + be[cn], cacc[mi][ni][3] + be[cn + 1]);
                *reinterpret_cast<float2*>(enct + (long)(rm + g) * H_ + cn) = p0;
                *reinterpret_cast<float2*>(enct + (long)(rm + g + 8) * H_ + cn) = p1;
            }
        }
    }
}

// ============ logits tf32 GEMM: M=512, N=1000 (pad 1024), K=512 =============
__global__ void logits_gemm_k(const float* __restrict__ A,      // comb, lda=512
                              const float* __restrict__ Bm,     // W_out [1000,512]
                              const float* __restrict__ bias,
                              float* __restrict__ C) {          // [512,1000]
    __shared__ unsigned AsT[2][16][65];
    __shared__ unsigned BsT[2][16][65];

    int tid = threadIdx.x;
    int lane = tid & 31, warp = tid >> 5;
    int g = lane >> 2, j = lane & 3;
    int m_off = (warp & 1) * 32, n_off = (warp >> 1) * 32;
    int sm = tid >> 1, sk = (tid & 1) * 8;
    int m0 = blockIdx.y * 64, n0 = blockIdx.x * 64;
    bool bn_ok = (n0 + sm) < V_;

    float cacc[2][4][4];
    #pragma unroll
    for (int mi = 0; mi < 2; mi++)
        #pragma unroll
        for (int ni = 0; ni < 4; ni++)
            #pragma unroll
            for (int q = 0; q < 4; q++) cacc[mi][ni][q] = 0.f;

    {
        const float4* ap = reinterpret_cast<const float4*>(A + (long)(m0 + sm) * (2 * H_) + sk);
        float4 a0 = ap[0], a1 = ap[1];
        float4 b0 = make_float4(0.f, 0.f, 0.f, 0.f), b1 = b0;
        if (bn_ok) {
            const float4* bp = reinterpret_cast<const float4*>(Bm + (long)(n0 + sm) * (2 * H_) + sk);
            b0 = bp[0]; b1 = bp[1];
        }
        STS8(AsT, 0, sk, sm, a0, a1);
        STS8(BsT, 0, sk, sm, b0, b1);
    }
    __syncthreads();
    for (int kt = 0; kt < 32; kt++) {
        int cur = kt & 1, nxt = cur ^ 1;
        bool more = (kt + 1 < 32);
        float4 va0, va1, vb0, vb1;
        if (more) {
            int gk = (kt + 1) * 16 + sk;
            const float4* ap = reinterpret_cast<const float4*>(A + (long)(m0 + sm) * (2 * H_) + gk);
            va0 = ap[0]; va1 = ap[1];
            vb0 = make_float4(0.f, 0.f, 0.f, 0.f); vb1 = vb0;
            if (bn_ok) {
                const float4* bp = reinterpret_cast<const float4*>(Bm + (long)(n0 + sm) * (2 * H_) + gk);
                vb0 = bp[0]; vb1 = bp[1];
            }
        }
        MMA_TILE(cur);
        if (more) {
            STS8(AsT, nxt, sk, sm, va0, va1);
            STS8(BsT, nxt, sk, sm, vb0, vb1);
        }
        __syncthreads();
    }
    #pragma unroll
    for (int mi = 0; mi < 2; mi++) {
        int rm = m0 + m_off + mi * 16;
        #pragma unroll
        for (int ni = 0; ni < 4; ni++) {
            int cn = n0 + n_off + ni * 8 + 2 * j;
            if (cn + 1 < V_) {
                float2 p0 = make_float2(cacc[mi][ni][0] + bias[cn], cacc[mi][ni][1] + bias[cn + 1]);
                float2 p1 = make_float2(cacc[mi][ni][2] + bias[cn], cacc[mi][ni][3] + bias[cn + 1]);
                *reinterpret_cast<float2*>(C + (long)(rm + g) * V_ + cn) = p0;
                *reinterpret_cast<float2*>(C + (long)(rm + g + 8) * V_ + cn) = p1;
            }
        }
    }
}

// ============================================================================
// Persistent LSTM, batch-parallel groups (R10, measured good).
// ============================================================================
#define LSTM_GRID 128
#define WSTRIDE 129
#define LSTM_SMEM ((64 * WSTRIDE + 128) * 16 + 256 * 4)

__global__ void lstm_persist_k(const float* __restrict__ h0,
                               const float* __restrict__ c0,
                               const float* __restrict__ xproj,
                               const float* __restrict__ W_hh,
                               const float* __restrict__ b_hh,
                               float* __restrict__ h_glob,
                               float* __restrict__ comb,
                               float* __restrict__ o_hT,
                               float* __restrict__ o_cT) {
    extern __shared__ float4 sm4[];
    float4* w4s = sm4;                       // [64][WSTRIDE]
    float4* h4s = sm4 + 64 * WSTRIDE;        // [2][64]
    float*  g_s = (float*)(h4s + 128);       // [128 cols][2]

    int tid = threadIdx.x;
    int grp = blockIdx.x >> 3;
    int blk = blockIdx.x & 7;

    const float4* W4 = reinterpret_cast<const float4*>(W_hh);
    for (int idx = tid; idx < 128 * 64; idx += 256) {
        int c = idx >> 6, k4 = idx & 63;
        int gcol = (c >> 5) * 256 + blk * 32 + (c & 31);
        w4s[k4 * WSTRIDE + c] = W4[(long)gcol * 64 + k4];
    }

    int pu = tid & 31, pbl = tid >> 5;
    int hh = blk * 32 + pu;
    int bb = grp * 2 + pbl;
    float c_reg = 0.f, bh0 = 0.f, bh1 = 0.f, bh2 = 0.f, bh3 = 0.f;
    if (tid < 64) {
        c_reg = c0[bb * H_ + hh];
        bh0 = b_hh[hh];           bh1 = b_hh[H_ + hh];
        bh2 = b_hh[2 * H_ + hh];  bh3 = b_hh[3 * H_ + hh];
    }

    int col = tid & 127, gb = tid >> 7;
    volatile unsigned int* flags = g_flags;

    for (int t = 0; t < T_; t++) {
        if (t > 0) {
            if (tid < 8) {
                unsigned int tgt = (unsigned int)t;
                while (flags[grp * 8 + tid] < tgt) {}
            }
        }
        __syncthreads();

        const float* hsrc = (t == 0) ? h0 : h_glob;
        if (tid < 128) {
            int b = tid >> 6, k4 = tid & 63;
            h4s[b * 64 + k4] =
                __ldcg(reinterpret_cast<const float4*>(hsrc + (grp * 2 + b) * H_) + k4);
        }
        float xg0 = 0.f, xg1 = 0.f, xg2 = 0.f, xg3 = 0.f;
        if (tid < 64) {
            const float* xp = xproj + (long)(t * B_ + bb) * (4 * H_);
            xg0 = xp[hh]; xg1 = xp[H_ + hh]; xg2 = xp[2 * H_ + hh]; xg3 = xp[3 * H_ + hh];
        }
        __syncthreads();

        {
            float4 p = make_float4(0.f, 0.f, 0.f, 0.f);
            const float4* hb = h4s + gb * 64;
            #pragma unroll 16
            for (int k4 = 0; k4 < 64; k4++) {
                float4 w = w4s[k4 * WSTRIDE + col];
                float4 hv = hb[k4];
                p.x = fmaf(w.x, hv.x, p.x);
                p.y = fmaf(w.y, hv.y, p.y);
                p.z = fmaf(w.z, hv.z, p.z);
                p.w = fmaf(w.w, hv.w, p.w);
            }
            g_s[col * 2 + gb] = (p.x + p.y) + (p.z + p.w);
        }
        __syncthreads();

        if (tid < 64) {
            float gi = g_s[(0 * 32 + pu) * 2 + pbl] + xg0 + bh0;
            float gf = g_s[(1 * 32 + pu) * 2 + pbl] + xg1 + bh1;
            float gg = g_s[(2 * 32 + pu) * 2 + pbl] + xg2 + bh2;
            float go = g_s[(3 * 32 + pu) * 2 + pbl] + xg3 + bh3;
            float si = 1.f / (1.f + __expf(-gi));
            float sf = 1.f / (1.f + __expf(-gf));
            float so = 1.f / (1.f + __expf(-go));
            c_reg = sf * c_reg + si * tanhf(gg);
            float hn = so * tanhf(c_reg);
            h_glob[bb * H_ + hh] = hn;
            comb[(long)(t * B_ + bb) * (2 * H_) + H_ + hh] = hn;
            if (t == T_ - 1) {
                o_hT[bb * H_ + hh] = hn;
                o_cT[bb * H_ + hh] = c_reg;
            }
        }

        if (t < T_ - 1) {
            __syncthreads();
            if (tid == 0) {
                __threadfence();
                g_flags[blockIdx.x] = (unsigned int)(t + 1);
            }
        }
    }
}

// ========== fused attention: dec matvec + scores + softmax + context ========
__device__ __forceinline__ float tanh_fast(float x) {
    float y;
    asm("tanh.approx.f32 %0, %1;" : "=f"(y) : "f"(x));
    return y;
}

__global__ void attn_fused_k(const float* __restrict__ enc_t,
                             const float* __restrict__ Wd,
                             const float* __restrict__ bd,
                             const float* __restrict__ wa,
                             const float* __restrict__ ba,
                             const int* __restrict__ lens,
                             const float* __restrict__ enc,
                             float* __restrict__ comb,
                             float* __restrict__ ctx_out) {
    int t = blockIdx.x / B_, b = blockIdx.x % B_;
    __shared__ float out_sh[H_], dec_sh[H_], wa_sh[H_], sc[S_], red[S_];
    int tid = threadIdx.x;
    int wrp = tid >> 5, lane = tid & 31;

    out_sh[tid] = comb[(long)(t * B_ + b) * (2 * H_) + H_ + tid];
    wa_sh[tid] = wa[tid];
    __syncthreads();

    {
        const float4* o4 = reinterpret_cast<const float4*>(out_sh);
        float4 oa = o4[lane], ob = o4[lane + 32];
        #pragma unroll 4
        for (int i = 0; i < 32; i++) {
            int hh = wrp * 32 + i;
            const float4* wr = reinterpret_cast<const float4*>(Wd + (long)hh * H_);
            float4 w0 = wr[lane], w1 = wr[lane + 32];
            float s = oa.x * w0.x + oa.y * w0.y + oa.z * w0.z + oa.w * w0.w
                    + ob.x * w1.x + ob.y * w1.y + ob.z * w1.z + ob.w * w1.w;
            #pragma unroll
            for (int o = 16; o; o >>= 1) s += __shfl_xor_sync(0xffffffffu, s, o);
            if (lane == 0) dec_sh[hh] = s + bd[hh];
        }
    }
    __syncthreads();

    float bav = ba[0];
    for (int s = wrp; s < S_; s += 8) {
        const float* er = enc_t + (long)(s * B_ + b) * H_;
        float sum = 0.f;
        #pragma unroll
        for (int i = 0; i < 8; i++) {
            int hh = lane + 32 * i;
            sum += tanh_fast(er[hh] + dec_sh[hh]) * wa_sh[hh];
        }
        #pragma unroll
        for (int o = 16; o; o >>= 1) sum += __shfl_xor_sync(0xffffffffu, sum, o);
        if (lane == 0) sc[s] = sum + bav;
    }
    __syncthreads();

    int len = lens[b];
    float v = (tid < len) ? sc[tid] : -1e30f;
    red[tid] = v; __syncthreads();
    for (int o = 128; o; o >>= 1) { if (tid < o) red[tid] = fmaxf(red[tid], red[tid + o]); __syncthreads(); }
    float m = red[0]; __syncthreads();
    float e = __expf(v - m);
    red[tid] = e; __syncthreads();
    for (int o = 128; o; o >>= 1) { if (tid < o) red[tid] += red[tid + o]; __syncthreads(); }
    float p = e * __fdividef(1.f, red[0]);
    __syncthreads();
    sc[tid] = p;
    __syncthreads();

    float sum = 0.f;
    const float* ep = enc + b * H_ + tid;
    #pragma unroll 4
    for (int s = 0; s < S_; s++)
        sum = fmaf(sc[s], ep[(long)s * B_ * H_], sum);
    comb[(long)(t * B_ + b) * (2 * H_) + tid] = sum;
    ctx_out[(long)(b * T_ + t) * H_ + tid] = sum;
}

// ---------------- softmax over V=1000 ----------------
__global__ void softmax_v_k(const float* __restrict__ logits, float* __restrict__ out) {
    int tb = blockIdx.x;
    int tid = threadIdx.x;
    __shared__ float red[256];
    const float* row = logits + (long)tb * V_;
    float m = -1e30f;
    for (int v = tid; v < V_; v += 256) m = fmaxf(m, row[v]);
    red[tid] = m; __syncthreads();
    for (int o = 128; o; o >>= 1) { if (tid < o) red[tid] = fmaxf(red[tid], red[tid + o]); __syncthreads(); }
    m = red[0]; __syncthreads();
    float sum = 0.f;
    for (int v = tid; v < V_; v += 256) {
        float e = __expf(row[v] - m);
        out[(long)tb * V_ + v] = e;
        sum += e;
    }
    red[tid] = sum; __syncthreads();
    for (int o = 128; o; o >>= 1) { if (tid < o) red[tid] += red[tid + o]; __syncthreads(); }
    float inv = __fdividef(1.f, red[0]);
    for (int v = tid; v < V_; v += 256) out[(long)tb * V_ + v] *= inv;
}

// ---------------- host ----------------
extern "C" void kernel_launch(void* const* d_in, const int* in_sizes, int n_in,
                              void* d_out, int out_size) {
    const int*   tv      = (const int*)  d_in[0];
    const float* h0      = (const float*)d_in[1];
    const float* c0      = (const float*)d_in[2];
    const float* enc     = (const float*)d_in[3];
    const int*   lens    = (const int*)  d_in[4];
    const float* emb     = (const float*)d_in[5];
    const float* W_ih    = (const float*)d_in[6];
    const float* W_hh    = (const float*)d_in[7];
    const float* b_ih    = (const float*)d_in[8];
    const float* b_hh    = (const float*)d_in[9];
    const float* We      = (const float*)d_in[10];
    const float* be      = (const float*)d_in[11];
    const float* Wd      = (const float*)d_in[12];
    const float* bd      = (const float*)d_in[13];
    const float* wa      = (const float*)d_in[14];
    const float* ba      = (const float*)d_in[15];
    const float* W_out   = (const float*)d_in[16];
    const float* b_out   = (const float*)d_in[17];

    float* scratch = nullptr;
    cudaGetSymbolAddress((void**)&scratch, g_scratch);
    unsigned int* flagsp = nullptr;
    cudaGetSymbolAddress((void**)&flagsp, g_flags);

    float* s_xproj  = scratch + OFF_XPROJ;
    float* s_h      = scratch + OFF_H;
    float* s_enct   = scratch + OFF_ENCT;
    float* s_comb   = scratch + OFF_COMB;
    float* s_logits = scratch + OFF_LOGITS;

    float* o_prob = (float*)d_out;
    float* o_hT   = o_prob + (long)T_ * B_ * V_;
    float* o_cT   = o_hT + B_ * H_;
    float* o_ctx  = o_cT + B_ * H_;

    // 0) reset group-barrier flags
    cudaMemsetAsync(flagsp, 0, 128 * sizeof(unsigned int));

    // 1) dual tf32 GEMM: xproj AND enc_t in one launch
    dual_gemm_k<<<640, 128>>>(emb, tv, W_ih, b_ih, s_xproj, enc, We, be, s_enct);

    // 2) persistent LSTM (batch-parallel groups, W-resident in smem)
    cudaFuncSetAttribute(lstm_persist_k, cudaFuncAttributeMaxDynamicSharedMemorySize, LSTM_SMEM);
    lstm_persist_k<<<LSTM_GRID, 256, LSTM_SMEM>>>(h0, c0, s_xproj, W_hh, b_hh,
                                                  s_h, s_comb, o_hT, o_cT);

    // 3) fused attention: dec matvec + scores + masked softmax + context
    attn_fused_k<<<T_ * B_, 256>>>(s_enct, Wd, bd, wa, ba, lens, enc, s_comb, o_ctx);

    // 4) logits = combined @ W_out^T + b_out : [512, 1000] (tf32)
    logits_gemm_k<<<dim3(16, 8), 128>>>(s_comb, W_out, b_out, s_logits);

    // 5) softmax over V -> output_prob
    softmax_v_k<<<T_ * B_, 256>>>(s_logits, o_prob);
}

// round 12
// speedup vs baseline: 2.8748x; 1.0469x over previous
#include <cuda_runtime.h>
#include <cuda_bf16.h>
#include <math.h>

#define T_ 16
#define B_ 32
#define S_ 256
#define H_ 256
#define E_ 300
#define V_ 1000

// ---------------- scratch arena (floats) ----------------
#define OFF_XPROJ   153600      // [T*B, 4H] = 512*1024
#define OFF_H       710656      // 32*256
#define OFF_ENCT    727040      // 8192*256
#define OFF_COMB    3086336     // 512*512
#define OFF_LOGITS  3348480     // 512*1000
#define SCRATCH_N   3860480

__device__ float g_scratch[SCRATCH_N];
__device__ unsigned int g_flags[128];

// ==================== tf32 mma helpers ====================
__device__ __forceinline__ unsigned f2tf(float x) {
    unsigned r; asm("cvt.rna.tf32.f32 %0, %1;" : "=r"(r) : "f"(x)); return r;
}
__device__ __forceinline__ void mma8(float* c, const unsigned* a, const unsigned* b) {
    asm("mma.sync.aligned.m16n8k8.row.col.f32.tf32.tf32.f32 "
        "{%0,%1,%2,%3}, {%4,%5,%6,%7}, {%8,%9}, {%0,%1,%2,%3};"
        : "+f"(c[0]), "+f"(c[1]), "+f"(c[2]), "+f"(c[3])
        : "r"(a[0]), "r"(a[1]), "r"(a[2]), "r"(a[3]), "r"(b[0]), "r"(b[1]));
}

// store 8 cvt'd floats into transposed smem tile [k][m]
#define STS8(DST, BUF, SK, SM, V0, V1)                  \
    DST[BUF][(SK) + 0][SM] = f2tf((V0).x);              \
    DST[BUF][(SK) + 1][SM] = f2tf((V0).y);              \
    DST[BUF][(SK) + 2][SM] = f2tf((V0).z);              \
    DST[BUF][(SK) + 3][SM] = f2tf((V0).w);              \
    DST[BUF][(SK) + 4][SM] = f2tf((V1).x);              \
    DST[BUF][(SK) + 5][SM] = f2tf((V1).y);              \
    DST[BUF][(SK) + 6][SM] = f2tf((V1).z);              \
    DST[BUF][(SK) + 7][SM] = f2tf((V1).w);

// one 64x64x32 tile of mma compute on buffer CUR (locals: AsT,BsT,cacc,g,j,m_off,n_off)
#define MMA_TILE32(CUR)                                                      \
    _Pragma("unroll")                                                        \
    for (int s = 0; s < 4; s++) {                                            \
        unsigned af[2][4], bf[4][2];                                         \
        _Pragma("unroll")                                                    \
        for (int mi = 0; mi < 2; mi++) {                                     \
            af[mi][0] = AsT[CUR][s * 8 + j    ][m_off + mi * 16 + g];        \
            af[mi][1] = AsT[CUR][s * 8 + j    ][m_off + mi * 16 + g + 8];    \
            af[mi][2] = AsT[CUR][s * 8 + j + 4][m_off + mi * 16 + g];        \
            af[mi][3] = AsT[CUR][s * 8 + j + 4][m_off + mi * 16 + g + 8];    \
        }                                                                    \
        _Pragma("unroll")                                                    \
        for (int ni = 0; ni < 4; ni++) {                                     \
            bf[ni][0] = BsT[CUR][s * 8 + j    ][n_off + ni * 8 + g];         \
            bf[ni][1] = BsT[CUR][s * 8 + j + 4][n_off + ni * 8 + g];         \
        }                                                                    \
        _Pragma("unroll")                                                    \
        for (int mi = 0; mi < 2; mi++)                                       \
            _Pragma("unroll")                                                \
            for (int ni = 0; ni < 4; ni++)                                   \
                mma8(cacc[mi][ni], af[mi], bf[ni]);                          \
    }

// ============================================================================
// Dual tf32 GEMM. 128-thread blocks, 64x64x32 tiles (BK=32).
// blocks [0,128):   xproj = emb[tv] @ W_ih^T + b_ih  (M=512,N=1024,K=300)
// blocks [128,640): enc_t = enc @ We^T + be          (M=8192,N=256,K=256)
// ============================================================================
__global__ void dual_gemm_k(const float* __restrict__ emb, const int* __restrict__ tv,
                            const float* __restrict__ W_ih, const float* __restrict__ b_ih,
                            float* __restrict__ xproj,
                            const float* __restrict__ enc, const float* __restrict__ We,
                            const float* __restrict__ be, float* __restrict__ enct) {
    __shared__ unsigned AsT[2][32][65];
    __shared__ unsigned BsT[2][32][65];
    __shared__ int rows_sh[64];

    int tid = threadIdx.x;
    int lane = tid & 31, warp = tid >> 5;
    int g = lane >> 2, j = lane & 3;
    int m_off = (warp & 1) * 32, n_off = (warp >> 1) * 32;
    int sm = tid >> 1, sk = (tid & 1) * 16;      // row, k-offset (16 per thread)
    int bid = blockIdx.x;

    float cacc[2][4][4];
    #pragma unroll
    for (int mi = 0; mi < 2; mi++)
        #pragma unroll
        for (int ni = 0; ni < 4; ni++)
            #pragma unroll
            for (int q = 0; q < 4; q++) cacc[mi][ni][q] = 0.f;

    if (bid < 128) {
        // -------- xproj: M=512, N=1024, K=300 (10 k-tiles, last ragged) -----
        int m0 = (bid >> 4) * 64, n0 = (bid & 15) * 64;
        if (tid < 64) rows_sh[tid] = tv[m0 + tid];
        __syncthreads();
        {
            const float4* ap = reinterpret_cast<const float4*>(emb + (long)rows_sh[sm] * E_ + sk);
            const float4* bp = reinterpret_cast<const float4*>(W_ih + (long)(n0 + sm) * E_ + sk);
            float4 a0 = ap[0], a1 = ap[1], a2 = ap[2], a3 = ap[3];
            float4 b0 = bp[0], b1 = bp[1], b2 = bp[2], b3 = bp[3];
            STS8(AsT, 0, sk, sm, a0, a1); STS8(AsT, 0, sk + 8, sm, a2, a3);
            STS8(BsT, 0, sk, sm, b0, b1); STS8(BsT, 0, sk + 8, sm, b2, b3);
        }
        __syncthreads();
        for (int kt = 0; kt < 10; kt++) {
            int cur = kt & 1, nxt = cur ^ 1;
            bool more = (kt + 1 < 10);
            float4 va[4], vb[4];
            if (more) {
                int gk = (kt + 1) * 32 + sk;
                if ((kt + 2) * 32 <= E_) {
                    const float4* ap = reinterpret_cast<const float4*>(emb + (long)rows_sh[sm] * E_ + gk);
                    const float4* bp = reinterpret_cast<const float4*>(W_ih + (long)(n0 + sm) * E_ + gk);
                    va[0] = ap[0]; va[1] = ap[1]; va[2] = ap[2]; va[3] = ap[3];
                    vb[0] = bp[0]; vb[1] = bp[1]; vb[2] = bp[2]; vb[3] = bp[3];
                } else {
                    const float* ar = emb + (long)rows_sh[sm] * E_;
                    const float* br = W_ih + (long)(n0 + sm) * E_;
                    float t[16], u[16];
                    #pragma unroll
                    for (int i = 0; i < 16; i++) {
                        int k = gk + i;
                        t[i] = (k < E_) ? ar[k] : 0.f;
                        u[i] = (k < E_) ? br[k] : 0.f;
                    }
                    #pragma unroll
                    for (int q = 0; q < 4; q++) {
                        va[q] = make_float4(t[4*q], t[4*q+1], t[4*q+2], t[4*q+3]);
                        vb[q] = make_float4(u[4*q], u[4*q+1], u[4*q+2], u[4*q+3]);
                    }
                }
            }
            MMA_TILE32(cur);
            if (more) {
                STS8(AsT, nxt, sk, sm, va[0], va[1]); STS8(AsT, nxt, sk + 8, sm, va[2], va[3]);
                STS8(BsT, nxt, sk, sm, vb[0], vb[1]); STS8(BsT, nxt, sk + 8, sm, vb[2], vb[3]);
            }
            __syncthreads();
        }
        #pragma unroll
        for (int mi = 0; mi < 2; mi++) {
            int rm = m0 + m_off + mi * 16;
            #pragma unroll
            for (int ni = 0; ni < 4; ni++) {
                int cn = n0 + n_off + ni * 8 + 2 * j;
                float2 p0 = make_float2(cacc[mi][ni][0] + b_ih[cn], cacc[mi][ni][1] + b_ih[cn + 1]);
                float2 p1 = make_float2(cacc[mi][ni][2] + b_ih[cn], cacc[mi][ni][3] + b_ih[cn + 1]);
                *reinterpret_cast<float2*>(xproj + (long)(rm + g) * (4 * H_) + cn) = p0;
                *reinterpret_cast<float2*>(xproj + (long)(rm + g + 8) * (4 * H_) + cn) = p1;
            }
        }
    } else {
        // -------- enc_t: M=8192, N=256, K=256 (8 clean k-tiles) -------------
        int r2 = bid - 128;
        int m0 = (r2 >> 2) * 64, n0 = (r2 & 3) * 64;
        {
            const float4* ap = reinterpret_cast<const float4*>(enc + (long)(m0 + sm) * H_ + sk);
            const float4* bp = reinterpret_cast<const float4*>(We + (long)(n0 + sm) * H_ + sk);
            float4 a0 = ap[0], a1 = ap[1], a2 = ap[2], a3 = ap[3];
            float4 b0 = bp[0], b1 = bp[1], b2 = bp[2], b3 = bp[3];
            STS8(AsT, 0, sk, sm, a0, a1); STS8(AsT, 0, sk + 8, sm, a2, a3);
            STS8(BsT, 0, sk, sm, b0, b1); STS8(BsT, 0, sk + 8, sm, b2, b3);
        }
        __syncthreads();
        for (int kt = 0; kt < 8; kt++) {
            int cur = kt & 1, nxt = cur ^ 1;
            bool more = (kt + 1 < 8);
            float4 va[4], vb[4];
            if (more) {
                int gk = (kt + 1) * 32 + sk;
                const float4* ap = reinterpret_cast<const float4*>(enc + (long)(m0 + sm) * H_ + gk);
                const float4* bp = reinterpret_cast<const float4*>(We + (long)(n0 + sm) * H_ + gk);
                va[0] = ap[0]; va[1] = ap[1]; va[2] = ap[2]; va[3] = ap[3];
                vb[0] = bp[0]; vb[1] = bp[1]; vb[2] = bp[2]; vb[3] = bp[3];
            }
            MMA_TILE32(cur);
            if (more) {
                STS8(AsT, nxt, sk, sm, va[0], va[1]); STS8(AsT, nxt, sk + 8, sm, va[2], va[3]);
                STS8(BsT, nxt, sk, sm, vb[0], vb[1]); STS8(BsT, nxt, sk + 8, sm, vb[2], vb[3]);
            }
            __syncthreads();
        }
        #pragma unroll
        for (int mi = 0; mi < 2; mi++) {
            int rm = m0 + m_off + mi * 16;
            #pragma unroll
            for (int ni = 0; ni < 4; ni++) {
                int cn = n0 + n_off + ni * 8 + 2 * j;
                float2 p0 = make_float2(cacc[mi][ni][0] + be[cn], cacc[mi][ni][1] + be[cn + 1]);
                float2 p1 = make_float2(cacc[mi][ni][2] + be[cn], cacc[mi][ni][3] + be[cn + 1]);
                *reinterpret_cast<float2*>(enct + (long)(rm + g) * H_ + cn) = p0;
                *reinterpret_cast<float2*>(enct + (long)(rm + g + 8) * H_ + cn) = p1;
            }
        }
    }
}

// ============ logits tf32 GEMM: M=512, N=1000 (pad 1024), K=512, BK=32 ======
__global__ void logits_gemm_k(const float* __restrict__ A,      // comb, lda=512
                              const float* __restrict__ Bm,     // W_out [1000,512]
                              const float* __restrict__ bias,
                              float* __restrict__ C) {          // [512,1000]
    __shared__ unsigned AsT[2][32][65];
    __shared__ unsigned BsT[2][32][65];

    int tid = threadIdx.x;
    int lane = tid & 31, warp = tid >> 5;
    int g = lane >> 2, j = lane & 3;
    int m_off = (warp & 1) * 32, n_off = (warp >> 1) * 32;
    int sm = tid >> 1, sk = (tid & 1) * 16;
    int m0 = blockIdx.y * 64, n0 = blockIdx.x * 64;
    bool bn_ok = (n0 + sm) < V_;

    float cacc[2][4][4];
    #pragma unroll
    for (int mi = 0; mi < 2; mi++)
        #pragma unroll
        for (int ni = 0; ni < 4; ni++)
            #pragma unroll
            for (int q = 0; q < 4; q++) cacc[mi][ni][q] = 0.f;

    {
        const float4* ap = reinterpret_cast<const float4*>(A + (long)(m0 + sm) * (2 * H_) + sk);
        float4 a0 = ap[0], a1 = ap[1], a2 = ap[2], a3 = ap[3];
        float4 z = make_float4(0.f, 0.f, 0.f, 0.f);
        float4 b0 = z, b1 = z, b2 = z, b3 = z;
        if (bn_ok) {
            const float4* bp = reinterpret_cast<const float4*>(Bm + (long)(n0 + sm) * (2 * H_) + sk);
            b0 = bp[0]; b1 = bp[1]; b2 = bp[2]; b3 = bp[3];
        }
        STS8(AsT, 0, sk, sm, a0, a1); STS8(AsT, 0, sk + 8, sm, a2, a3);
        STS8(BsT, 0, sk, sm, b0, b1); STS8(BsT, 0, sk + 8, sm, b2, b3);
    }
    __syncthreads();
    for (int kt = 0; kt < 16; kt++) {
        int cur = kt & 1, nxt = cur ^ 1;
        bool more = (kt + 1 < 16);
        float4 va[4], vb[4];
        if (more) {
            int gk = (kt + 1) * 32 + sk;
            const float4* ap = reinterpret_cast<const float4*>(A + (long)(m0 + sm) * (2 * H_) + gk);
            va[0] = ap[0]; va[1] = ap[1]; va[2] = ap[2]; va[3] = ap[3];
            float4 z = make_float4(0.f, 0.f, 0.f, 0.f);
            vb[0] = z; vb[1] = z; vb[2] = z; vb[3] = z;
            if (bn_ok) {
                const float4* bp = reinterpret_cast<const float4*>(Bm + (long)(n0 + sm) * (2 * H_) + gk);
                vb[0] = bp[0]; vb[1] = bp[1]; vb[2] = bp[2]; vb[3] = bp[3];
            }
        }
        MMA_TILE32(cur);
        if (more) {
            STS8(AsT, nxt, sk, sm, va[0], va[1]); STS8(AsT, nxt, sk + 8, sm, va[2], va[3]);
            STS8(BsT, nxt, sk, sm, vb[0], vb[1]); STS8(BsT, nxt, sk + 8, sm, vb[2], vb[3]);
        }
        __syncthreads();
    }
    #pragma unroll
    for (int mi = 0; mi < 2; mi++) {
        int rm = m0 + m_off + mi * 16;
        #pragma unroll
        for (int ni = 0; ni < 4; ni++) {
            int cn = n0 + n_off + ni * 8 + 2 * j;
            if (cn + 1 < V_) {
                float2 p0 = make_float2(cacc[mi][ni][0] + bias[cn], cacc[mi][ni][1] + bias[cn + 1]);
                float2 p1 = make_float2(cacc[mi][ni][2] + bias[cn], cacc[mi][ni][3] + bias[cn + 1]);
                *reinterpret_cast<float2*>(C + (long)(rm + g) * V_ + cn) = p0;
                *reinterpret_cast<float2*>(C + (long)(rm + g + 8) * V_ + cn) = p1;
            }
        }
    }
}

// ============================================================================
// Persistent LSTM, batch-parallel groups, k-split W-dedup.
// 128 blocks = 16 groups x 8. Block owns 128 gate cols for 2 batches.
// Thread = (col, k-half): reads each w element ONCE, applies to both batches
// (h loads broadcast). Partials combined in the pointwise stage.
// ============================================================================
#define LSTM_GRID 128
#define WSTRIDE 129
#define LSTM_SMEM ((64 * WSTRIDE + 128) * 16 + 2 * 256 * 4)

__global__ void lstm_persist_k(const float* __restrict__ h0,
                               const float* __restrict__ c0,
                               const float* __restrict__ xproj,
                               const float* __restrict__ W_hh,
                               const float* __restrict__ b_hh,
                               float* __restrict__ h_glob,
                               float* __restrict__ comb,
                               float* __restrict__ o_hT,
                               float* __restrict__ o_cT) {
    extern __shared__ float4 sm4[];
    float4* w4s = sm4;                       // [64][WSTRIDE]
    float4* h4s = sm4 + 64 * WSTRIDE;        // [2][64]
    float*  part = (float*)(h4s + 128);      // [2 kh][128 col * 2 gb]

    int tid = threadIdx.x;
    int grp = blockIdx.x >> 3;
    int blk = blockIdx.x & 7;

    const float4* W4 = reinterpret_cast<const float4*>(W_hh);
    for (int idx = tid; idx < 128 * 64; idx += 256) {
        int c = idx >> 6, k4 = idx & 63;
        int gcol = (c >> 5) * 256 + blk * 32 + (c & 31);
        w4s[k4 * WSTRIDE + c] = W4[(long)gcol * 64 + k4];
    }

    int pu = tid & 31, pbl = tid >> 5;
    int hh = blk * 32 + pu;
    int bb = grp * 2 + pbl;
    float c_reg = 0.f, bh0 = 0.f, bh1 = 0.f, bh2 = 0.f, bh3 = 0.f;
    if (tid < 64) {
        c_reg = c0[bb * H_ + hh];
        bh0 = b_hh[hh];           bh1 = b_hh[H_ + hh];
        bh2 = b_hh[2 * H_ + hh];  bh3 = b_hh[3 * H_ + hh];
    }

    int col = tid & 127, kh = tid >> 7;      // k-half in {0,1}
    int kbase = kh * 32;                     // float4 k-offset
    volatile unsigned int* flags = g_flags;

    for (int t = 0; t < T_; t++) {
        if (t > 0) {
            if (tid < 8) {
                unsigned int tgt = (unsigned int)t;
                while (flags[grp * 8 + tid] < tgt) {}
            }
        }
        __syncthreads();

        const float* hsrc = (t == 0) ? h0 : h_glob;
        if (tid < 128) {
            int b = tid >> 6, k4 = tid & 63;
            h4s[b * 64 + k4] =
                __ldcg(reinterpret_cast<const float4*>(hsrc + (grp * 2 + b) * H_) + k4);
        }
        float xg0 = 0.f, xg1 = 0.f, xg2 = 0.f, xg3 = 0.f;
        if (tid < 64) {
            const float* xp = xproj + (long)(t * B_ + bb) * (4 * H_);
            xg0 = xp[hh]; xg1 = xp[H_ + hh]; xg2 = xp[2 * H_ + hh]; xg3 = xp[3 * H_ + hh];
        }
        __syncthreads();

        // half-K dot products for BOTH batches; w read once per element
        {
            float4 p0 = make_float4(0.f, 0.f, 0.f, 0.f);
            float4 p1 = make_float4(0.f, 0.f, 0.f, 0.f);
            const float4* hb0 = h4s;
            const float4* hb1 = h4s + 64;
            #pragma unroll 8
            for (int k4 = 0; k4 < 32; k4++) {
                float4 w = w4s[(kbase + k4) * WSTRIDE + col];
                float4 ha = hb0[kbase + k4];
                float4 hbv = hb1[kbase + k4];
                p0.x = fmaf(w.x, ha.x, p0.x);
                p0.y = fmaf(w.y, ha.y, p0.y);
                p0.z = fmaf(w.z, ha.z, p0.z);
                p0.w = fmaf(w.w, ha.w, p0.w);
                p1.x = fmaf(w.x, hbv.x, p1.x);
                p1.y = fmaf(w.y, hbv.y, p1.y);
                p1.z = fmaf(w.z, hbv.z, p1.z);
                p1.w = fmaf(w.w, hbv.w, p1.w);
            }
            part[kh * 256 + col * 2 + 0] = (p0.x + p0.y) + (p0.z + p0.w);
            part[kh * 256 + col * 2 + 1] = (p1.x + p1.y) + (p1.z + p1.w);
        }
        __syncthreads();

        if (tid < 64) {
            int i0 = (0 * 32 + pu) * 2 + pbl;
            int i1 = (1 * 32 + pu) * 2 + pbl;
            int i2 = (2 * 32 + pu) * 2 + pbl;
            int i3 = (3 * 32 + pu) * 2 + pbl;
            float gi = part[i0] + part[256 + i0] + xg0 + bh0;
            float gf = part[i1] + part[256 + i1] + xg1 + bh1;
            float gg = part[i2] + part[256 + i2] + xg2 + bh2;
            float go = part[i3] + part[256 + i3] + xg3 + bh3;
            float si = 1.f / (1.f + __expf(-gi));
            float sf = 1.f / (1.f + __expf(-gf));
            float so = 1.f / (1.f + __expf(-go));
            c_reg = sf * c_reg + si * tanhf(gg);
            float hn = so * tanhf(c_reg);
            h_glob[bb * H_ + hh] = hn;
            comb[(long)(t * B_ + bb) * (2 * H_) + H_ + hh] = hn;
            if (t == T_ - 1) {
                o_hT[bb * H_ + hh] = hn;
                o_cT[bb * H_ + hh] = c_reg;
            }
        }

        if (t < T_ - 1) {
            __syncthreads();
            if (tid == 0) {
                __threadfence();
                g_flags[blockIdx.x] = (unsigned int)(t + 1);
            }
        }
    }
}

// ========== fused attention: dec matvec + scores + softmax + context ========
__device__ __forceinline__ float tanh_fast(float x) {
    float y;
    asm("tanh.approx.f32 %0, %1;" : "=f"(y) : "f"(x));
    return y;
}

__global__ void attn_fused_k(const float* __restrict__ enc_t,
                             const float* __restrict__ Wd,
                             const float* __restrict__ bd,
                             const float* __restrict__ wa,
                             const float* __restrict__ ba,
                             const int* __restrict__ lens,
                             const float* __restrict__ enc,
                             float* __restrict__ comb,
                             float* __restrict__ ctx_out) {
    int t = blockIdx.x / B_, b = blockIdx.x % B_;
    __shared__ float out_sh[H_], dec_sh[H_], wa_sh[H_], sc[S_], red[S_];
    int tid = threadIdx.x;
    int wrp = tid >> 5, lane = tid & 31;

    out_sh[tid] = comb[(long)(t * B_ + b) * (2 * H_) + H_ + tid];
    wa_sh[tid] = wa[tid];
    __syncthreads();

    {
        const float4* o4 = reinterpret_cast<const float4*>(out_sh);
        float4 oa = o4[lane], ob = o4[lane + 32];
        #pragma unroll 4
        for (int i = 0; i < 32; i++) {
            int hh = wrp * 32 + i;
            const float4* wr = reinterpret_cast<const float4*>(Wd + (long)hh * H_);
            float4 w0 = wr[lane], w1 = wr[lane + 32];
            float s = oa.x * w0.x + oa.y * w0.y + oa.z * w0.z + oa.w * w0.w
                    + ob.x * w1.x + ob.y * w1.y + ob.z * w1.z + ob.w * w1.w;
            #pragma unroll
            for (int o = 16; o; o >>= 1) s += __shfl_xor_sync(0xffffffffu, s, o);
            if (lane == 0) dec_sh[hh] = s + bd[hh];
        }
    }
    __syncthreads();

    float bav = ba[0];
    for (int s = wrp; s < S_; s += 8) {
        const float* er = enc_t + (long)(s * B_ + b) * H_;
        float sum = 0.f;
        #pragma unroll
        for (int i = 0; i < 8; i++) {
            int hh = lane + 32 * i;
            sum += tanh_fast(er[hh] + dec_sh[hh]) * wa_sh[hh];
        }
        #pragma unroll
        for (int o = 16; o; o >>= 1) sum += __shfl_xor_sync(0xffffffffu, sum, o);
        if (lane == 0) sc[s] = sum + bav;
    }
    __syncthreads();

    int len = lens[b];
    float v = (tid < len) ? sc[tid] : -1e30f;
    red[tid] = v; __syncthreads();
    for (int o = 128; o; o >>= 1) { if (tid < o) red[tid] = fmaxf(red[tid], red[tid + o]); __syncthreads(); }
    float m = red[0]; __syncthreads();
    float e = __expf(v - m);
    red[tid] = e; __syncthreads();
    for (int o = 128; o; o >>= 1) { if (tid < o) red[tid] += red[tid + o]; __syncthreads(); }
    float p = e * __fdividef(1.f, red[0]);
    __syncthreads();
    sc[tid] = p;
    __syncthreads();

    float sum = 0.f;
    const float* ep = enc + b * H_ + tid;
    #pragma unroll 4
    for (int s = 0; s < S_; s++)
        sum = fmaf(sc[s], ep[(long)s * B_ * H_], sum);
    comb[(long)(t * B_ + b) * (2 * H_) + tid] = sum;
    ctx_out[(long)(b * T_ + t) * H_ + tid] = sum;
}

// ---------------- softmax over V=1000 ----------------
__global__ void softmax_v_k(const float* __restrict__ logits, float* __restrict__ out) {
    int tb = blockIdx.x;
    int tid = threadIdx.x;
    __shared__ float red[256];
    const float* row = logits + (long)tb * V_;
    float m = -1e30f;
    for (int v = tid; v < V_; v += 256) m = fmaxf(m, row[v]);
    red[tid] = m; __syncthreads();
    for (int o = 128; o; o >>= 1) { if (tid < o) red[tid] = fmaxf(red[tid], red[tid + o]); __syncthreads(); }
    m = red[0]; __syncthreads();
    float sum = 0.f;
    for (int v = tid; v < V_; v += 256) {
        float e = __expf(row[v] - m);
        out[(long)tb * V_ + v] = e;
        sum += e;
    }
    red[tid] = sum; __syncthreads();
    for (int o = 128; o; o >>= 1) { if (tid < o) red[tid] += red[tid + o]; __syncthreads(); }
    float inv = __fdividef(1.f, red[0]);
    for (int v = tid; v < V_; v += 256) out[(long)tb * V_ + v] *= inv;
}

// ---------------- host ----------------
extern "C" void kernel_launch(void* const* d_in, const int* in_sizes, int n_in,
                              void* d_out, int out_size) {
    const int*   tv      = (const int*)  d_in[0];
    const float* h0      = (const float*)d_in[1];
    const float* c0      = (const float*)d_in[2];
    const float* enc     = (const float*)d_in[3];
    const int*   lens    = (const int*)  d_in[4];
    const float* emb     = (const float*)d_in[5];
    const float* W_ih    = (const float*)d_in[6];
    const float* W_hh    = (const float*)d_in[7];
    const float* b_ih    = (const float*)d_in[8];
    const float* b_hh    = (const float*)d_in[9];
    const float* We      = (const float*)d_in[10];
    const float* be      = (const float*)d_in[11];
    const float* Wd      = (const float*)d_in[12];
    const float* bd      = (const float*)d_in[13];
    const float* wa      = (const float*)d_in[14];
    const float* ba      = (const float*)d_in[15];
    const float* W_out   = (const float*)d_in[16];
    const float* b_out   = (const float*)d_in[17];

    float* scratch = nullptr;
    cudaGetSymbolAddress((void**)&scratch, g_scratch);
    unsigned int* flagsp = nullptr;
    cudaGetSymbolAddress((void**)&flagsp, g_flags);

    float* s_xproj  = scratch + OFF_XPROJ;
    float* s_h      = scratch + OFF_H;
    float* s_enct   = scratch + OFF_ENCT;
    float* s_comb   = scratch + OFF_COMB;
    float* s_logits = scratch + OFF_LOGITS;

    float* o_prob = (float*)d_out;
    float* o_hT   = o_prob + (long)T_ * B_ * V_;
    float* o_cT   = o_hT + B_ * H_;
    float* o_ctx  = o_cT + B_ * H_;

    // 0) reset group-barrier flags
    cudaMemsetAsync(flagsp, 0, 128 * sizeof(unsigned int));

    // 1) dual tf32 GEMM (BK=32): xproj AND enc_t in one launch
    dual_gemm_k<<<640, 128>>>(emb, tv, W_ih, b_ih, s_xproj, enc, We, be, s_enct);

    // 2) persistent LSTM (k-split W-dedup)
    cudaFuncSetAttribute(lstm_persist_k, cudaFuncAttributeMaxDynamicSharedMemorySize, LSTM_SMEM);
    lstm_persist_k<<<LSTM_GRID, 256, LSTM_SMEM>>>(h0, c0, s_xproj, W_hh, b_hh,
                                                  s_h, s_comb, o_hT, o_cT);

    // 3) fused attention: dec matvec + scores + masked softmax + context
    attn_fused_k<<<T_ * B_, 256>>>(s_enct, Wd, bd, wa, ba, lens, enc, s_comb, o_ctx);

    // 4) logits = combined @ W_out^T + b_out : [512, 1000] (tf32, BK=32)
    logits_gemm_k<<<dim3(16, 8), 128>>>(s_comb, W_out, b_out, s_logits);

    // 5) softmax over V -> output_prob
    softmax_v_k<<<T_ * B_, 256>>>(s_logits, o_prob);
}